// round 10
// baseline (speedup 1.0000x reference)
#include <cuda_runtime.h>
#include <cuda_bf16.h>
#include <math.h>

// Problem constants (fixed by the reference)
#define BATCH 2
#define SEQ   2048
#define DMODEL 1024
#define NHEAD 16
#define HD    64          // head dim
#define QKV_ROW (3*DMODEL)

typedef unsigned int uint32;

// ---- mma / ldmatrix / cp.async wrappers -----------------------------------
__device__ __forceinline__ void ldsm_x4(uint32 r[4], uint32 addr) {
    asm volatile("ldmatrix.sync.aligned.m8n8.x4.shared.b16 {%0,%1,%2,%3}, [%4];"
                 : "=r"(r[0]), "=r"(r[1]), "=r"(r[2]), "=r"(r[3]) : "r"(addr));
}
__device__ __forceinline__ void ldsm_x4_t(uint32 r[4], uint32 addr) {
    asm volatile("ldmatrix.sync.aligned.m8n8.x4.trans.shared.b16 {%0,%1,%2,%3}, [%4];"
                 : "=r"(r[0]), "=r"(r[1]), "=r"(r[2]), "=r"(r[3]) : "r"(addr));
}
__device__ __forceinline__ void mma_bf16(float d[4], const uint32 a[4],
                                         uint32 b0, uint32 b1) {
    asm volatile(
        "mma.sync.aligned.m16n8k16.row.col.f32.bf16.bf16.f32 "
        "{%0,%1,%2,%3}, {%4,%5,%6,%7}, {%8,%9}, {%10,%11,%12,%13};"
        : "=f"(d[0]), "=f"(d[1]), "=f"(d[2]), "=f"(d[3])
        : "r"(a[0]), "r"(a[1]), "r"(a[2]), "r"(a[3]),
          "r"(b0), "r"(b1),
          "f"(d[0]), "f"(d[1]), "f"(d[2]), "f"(d[3]));
}
__device__ __forceinline__ void cp16(uint32 smem_addr, const void* gptr) {
    asm volatile("cp.async.ca.shared.global [%0], [%1], 16;\n"
                 :: "r"(smem_addr), "l"(gptr));
}
__device__ __forceinline__ void cp_commit() {
    asm volatile("cp.async.commit_group;\n");
}
template<int N> __device__ __forceinline__ void cp_wait() {
    asm volatile("cp.async.wait_group %0;\n" :: "n"(N));
}

// split one float pair -> packed bf16x2 hi + packed bf16x2 lo
__device__ __forceinline__ void split2(float x, float y, uint32 &hi, uint32 &lo) {
    __nv_bfloat162 h2 = __floats2bfloat162_rn(x, y);
    hi = *reinterpret_cast<uint32*>(&h2);
    float rx = x - __bfloat162float(h2.x);
    float ry = y - __bfloat162float(h2.y);
    __nv_bfloat162 l2 = __floats2bfloat162_rn(rx, ry);
    lo = *reinterpret_cast<uint32*>(&l2);
}

// Scratch (allocation-free rule: __device__ globals)
__device__ __nv_bfloat16 g_hid_h[(size_t)BATCH*SEQ*DMODEL];
__device__ __nv_bfloat16 g_hid_l[(size_t)BATCH*SEQ*DMODEL];
__device__ __nv_bfloat16 g_wa_h[(size_t)DMODEL*3*DMODEL];
__device__ __nv_bfloat16 g_wa_l[(size_t)DMODEL*3*DMODEL];
__device__ __nv_bfloat16 g_wp_h[(size_t)DMODEL*DMODEL];
__device__ __nv_bfloat16 g_wp_l[(size_t)DMODEL*DMODEL];
__device__ __nv_bfloat16 g_at_h[(size_t)BATCH*SEQ*DMODEL];
__device__ __nv_bfloat16 g_at_l[(size_t)BATCH*SEQ*DMODEL];
// head-major [B][H][S][HD] bf16 splits of q (pre-scaled by 1/8), k, v
#define HEADS_ELEMS ((size_t)BATCH*NHEAD*SEQ*HD)
__device__ __nv_bfloat16 g_q_h[HEADS_ELEMS];
__device__ __nv_bfloat16 g_q_l[HEADS_ELEMS];
__device__ __nv_bfloat16 g_k_h[HEADS_ELEMS];
__device__ __nv_bfloat16 g_k_l[HEADS_ELEMS];
__device__ __nv_bfloat16 g_v_h[HEADS_ELEMS];
__device__ __nv_bfloat16 g_v_l[HEADS_ELEMS];

// ---------------------------------------------------------------------------
// fp32 -> (bf16 hi, bf16 lo) split (flat arrays).
// ---------------------------------------------------------------------------
__global__ __launch_bounds__(256)
void split_kernel(const float* __restrict__ x,
                  __nv_bfloat16* __restrict__ hi,
                  __nv_bfloat16* __restrict__ lo, int n)
{
    int i = (blockIdx.x * 256 + threadIdx.x) * 4;
    if (i >= n) return;
    float4 v = *(const float4*)&x[i];
    uint32 h0, l0, h1, l1;
    split2(v.x, v.y, h0, l0);
    split2(v.z, v.w, h1, l1);
    *(uint32*)&hi[i]     = h0;
    *(uint32*)&hi[i + 2] = h1;
    *(uint32*)&lo[i]     = l0;
    *(uint32*)&lo[i + 2] = l1;
}

// ---------------------------------------------------------------------------
// Tensor-core GEMM (bf16 3-term split, fp32 accumulate), cp.async double
// buffered.  512 threads / 16 warps (4m x 4n), warp tile 32x32 -> 4 warps
// per SMSP to cover mma/ldmatrix latency.
// MODE 0: epilogue = bias + fp32 store to C.
// MODE 1: epilogue = bias, q-scale, bf16 hi/lo split, head-major scatter.
// BM=128, BN=128, BK=32.
// ---------------------------------------------------------------------------
#define GEMM_SMEM_BYTES (4736 * 16)
template<int MODE>
__global__ __launch_bounds__(512, 1)
void gemm_mma_kernel(const __nv_bfloat16* __restrict__ Ah,
                     const __nv_bfloat16* __restrict__ Al,
                     const __nv_bfloat16* __restrict__ Wh,
                     const __nv_bfloat16* __restrict__ Wl,
                     const float* __restrict__ bias,
                     float* __restrict__ C,
                     __nv_bfloat16* __restrict__ Qh, __nv_bfloat16* __restrict__ Ql,
                     __nv_bfloat16* __restrict__ Kh, __nv_bfloat16* __restrict__ Kl,
                     __nv_bfloat16* __restrict__ Vh, __nv_bfloat16* __restrict__ Vl,
                     int M, int N, int K)
{
    extern __shared__ uint4 dsm[];
    uint32 base = (uint32)__cvta_generic_to_shared(dsm);
    const uint32 oAh = 0, oAl = 20480, oWh = 40960, oWl = 58368;
    const uint32 stA = 10240, stW = 8704;   // per-stage byte strides

    const int tid  = threadIdx.x;
    const int lane = tid & 31;
    const int wid  = tid >> 5;
    const int warp_m = wid & 3;          // 4 x 32-row slices
    const int warp_n = wid >> 2;         // 4 x 32-col slices
    const int row0 = blockIdx.y * 128;
    const int col0 = blockIdx.x * 128;

    // ldmatrix lane offsets
    const int j  = lane & 7;
    const int q  = lane >> 3;
    const int a_row_off = j + (q & 1) * 8;
    const int a_chk_off = q >> 1;
    uint32 aOff[2];
    #pragma unroll
    for (int ma = 0; ma < 2; ma++) {
        int r = warp_m * 32 + ma * 16 + a_row_off;
        aOff[ma] = (uint32)(r * 5 + a_chk_off) * 16;
    }
    uint32 wOff[2];
    #pragma unroll
    for (int nb = 0; nb < 2; nb++) {
        int k = j + (q & 1) * 8;
        int chk = (warp_n * 32 + nb * 16) / 8 + (q >> 1);
        wOff[nb] = (uint32)(k * 17 + chk) * 16;
    }

    // loader coordinates: exactly one 16B chunk per array per thread
    const int aR = tid >> 2, aC = tid & 3;      // 128 x 4
    const int wR = tid >> 4, wC = tid & 15;     // 32 x 16

    float acc[2][4][4];
    #pragma unroll
    for (int ma = 0; ma < 2; ma++)
        #pragma unroll
        for (int na = 0; na < 4; na++)
            #pragma unroll
            for (int i = 0; i < 4; i++)
                acc[ma][na][i] = 0.f;

    const int nkt = K / 32;
    // prologue: stage 0
    cp16(base + oAh + (uint32)(aR * 5 + aC) * 16,
         &Ah[(size_t)(row0 + aR) * K + aC * 8]);
    cp16(base + oAl + (uint32)(aR * 5 + aC) * 16,
         &Al[(size_t)(row0 + aR) * K + aC * 8]);
    cp16(base + oWh + (uint32)(wR * 17 + wC) * 16,
         &Wh[(size_t)wR * N + col0 + wC * 8]);
    cp16(base + oWl + (uint32)(wR * 17 + wC) * 16,
         &Wl[(size_t)wR * N + col0 + wC * 8]);
    cp_commit();

    for (int kt = 0; kt < nkt; kt++) {
        if (kt + 1 < nkt) {
            uint32 st = (uint32)((kt + 1) & 1);
            int k0n = (kt + 1) * 32;
            cp16(base + oAh + st * stA + (uint32)(aR * 5 + aC) * 16,
                 &Ah[(size_t)(row0 + aR) * K + k0n + aC * 8]);
            cp16(base + oAl + st * stA + (uint32)(aR * 5 + aC) * 16,
                 &Al[(size_t)(row0 + aR) * K + k0n + aC * 8]);
            cp16(base + oWh + st * stW + (uint32)(wR * 17 + wC) * 16,
                 &Wh[(size_t)(k0n + wR) * N + col0 + wC * 8]);
            cp16(base + oWl + st * stW + (uint32)(wR * 17 + wC) * 16,
                 &Wl[(size_t)(k0n + wR) * N + col0 + wC * 8]);
            cp_commit();
            cp_wait<1>();
        } else {
            cp_wait<0>();
        }
        __syncthreads();

        uint32 st = (uint32)(kt & 1);
        uint32 bAh = base + oAh + st * stA;
        uint32 bAl = base + oAl + st * stA;
        uint32 bWh = base + oWh + st * stW;
        uint32 bWl = base + oWl + st * stW;

        #pragma unroll
        for (int ks = 0; ks < 2; ks++) {
            uint32 ah[2][4], al[2][4], bh[2][4], bl[2][4];
            ldsm_x4(ah[0], bAh + aOff[0] + ks * 32);
            ldsm_x4(ah[1], bAh + aOff[1] + ks * 32);
            ldsm_x4(al[0], bAl + aOff[0] + ks * 32);
            ldsm_x4(al[1], bAl + aOff[1] + ks * 32);
            ldsm_x4_t(bh[0], bWh + wOff[0] + ks * 4352);   // +16 k-rows * 272B
            ldsm_x4_t(bh[1], bWh + wOff[1] + ks * 4352);
            ldsm_x4_t(bl[0], bWl + wOff[0] + ks * 4352);
            ldsm_x4_t(bl[1], bWl + wOff[1] + ks * 4352);
            // pass 1: Ah*Wh — 8 mma, distinct accumulators
            #pragma unroll
            for (int nb = 0; nb < 2; nb++)
                #pragma unroll
                for (int ma = 0; ma < 2; ma++) {
                    mma_bf16(acc[ma][2*nb],   ah[ma], bh[nb][0], bh[nb][1]);
                    mma_bf16(acc[ma][2*nb+1], ah[ma], bh[nb][2], bh[nb][3]);
                }
            // pass 2: Ah*Wl
            #pragma unroll
            for (int nb = 0; nb < 2; nb++)
                #pragma unroll
                for (int ma = 0; ma < 2; ma++) {
                    mma_bf16(acc[ma][2*nb],   ah[ma], bl[nb][0], bl[nb][1]);
                    mma_bf16(acc[ma][2*nb+1], ah[ma], bl[nb][2], bl[nb][3]);
                }
            // pass 3: Al*Wh
            #pragma unroll
            for (int nb = 0; nb < 2; nb++)
                #pragma unroll
                for (int ma = 0; ma < 2; ma++) {
                    mma_bf16(acc[ma][2*nb],   al[ma], bh[nb][0], bh[nb][1]);
                    mma_bf16(acc[ma][2*nb+1], al[ma], bh[nb][2], bh[nb][3]);
                }
        }
        __syncthreads();
    }

    // ---- epilogue ----
    int r_base = row0 + warp_m * 32 + (lane >> 2);
    int c_base = col0 + warp_n * 32 + (lane & 3) * 2;
    #pragma unroll
    for (int ma = 0; ma < 2; ma++) {
        #pragma unroll
        for (int na = 0; na < 4; na++) {
            int c = c_base + na * 8;
            float bx = bias[c], by = bias[c + 1];
            #pragma unroll
            for (int half = 0; half < 2; half++) {
                int r = r_base + ma * 16 + half * 8;
                float vx = acc[ma][na][2 * half + 0] + bx;
                float vy = acc[ma][na][2 * half + 1] + by;
                if (MODE == 0) {
                    *(float2*)&C[(size_t)r * N + c] = make_float2(vx, vy);
                } else {
                    int arr = c >> 10;               // 0=q 1=k 2=v
                    int hh  = (c >> 6) & 15;
                    int dd  = c & 63;
                    int bb  = r >> 11, ss = r & 2047;
                    size_t dst = (((size_t)(bb * NHEAD + hh)) * SEQ + ss) * HD + dd;
                    if (arr == 0) { vx *= 0.125f; vy *= 0.125f; }
                    uint32 hi, lo;
                    split2(vx, vy, hi, lo);
                    __nv_bfloat16* ph = (arr == 0) ? Qh : (arr == 1) ? Kh : Vh;
                    __nv_bfloat16* pl = (arr == 0) ? Ql : (arr == 1) ? Kl : Vl;
                    *(uint32*)&ph[dst] = hi;
                    *(uint32*)&pl[dst] = lo;
                }
            }
        }
    }
}

// ---------------------------------------------------------------------------
// MMA causal flash attention (bf16 3-term splits, fp32 softmax/accum),
// epilogue writes bf16 hi/lo split directly.
// BM=128 q rows/block, BN=64 keys/tile, 8 warps (warp = 16 q rows).
// ---------------------------------------------------------------------------
#define ATTN_SMEM_BYTES (2 * 36864)
__global__ __launch_bounds__(256, 1)
void attn_mma_kernel(const __nv_bfloat16* __restrict__ Qh,
                     const __nv_bfloat16* __restrict__ Ql,
                     const __nv_bfloat16* __restrict__ Kh,
                     const __nv_bfloat16* __restrict__ Kl,
                     const __nv_bfloat16* __restrict__ Vh,
                     const __nv_bfloat16* __restrict__ Vl,
                     __nv_bfloat16* __restrict__ Oh,
                     __nv_bfloat16* __restrict__ Ol)
{
    extern __shared__ uint4 dsm[];
    uint32 smem_u = (uint32)__cvta_generic_to_shared(dsm);

    const int tid  = threadIdx.x;
    const int lane = tid & 31;
    const int wq   = tid >> 5;
    const int qt = (int)gridDim.x - 1 - (int)blockIdx.x;
    const int h = blockIdx.y, b = blockIdx.z;
    const int q0 = qt * 128;
    const size_t headoff = ((size_t)(b * NHEAD + h)) * SEQ * HD;

    const int gid = lane >> 2;           // 0..7
    const int tig = lane & 3;            // 0..3
    const int row0 = q0 + wq * 16 + gid; // absolute q row (c0/c1); row1 = row0+8

    // ---- Q fragments straight from global ----
    uint32 qh[4][4], ql[4][4];
    {
        const __nv_bfloat16* Qhb = Qh + headoff;
        const __nv_bfloat16* Qlb = Ql + headoff;
        #pragma unroll
        for (int ks = 0; ks < 4; ks++) {
            int kc = ks * 16 + 2 * tig;
            qh[ks][0] = *(const uint32*)&Qhb[(size_t)row0 * HD + kc];
            qh[ks][1] = *(const uint32*)&Qhb[(size_t)(row0 + 8) * HD + kc];
            qh[ks][2] = *(const uint32*)&Qhb[(size_t)row0 * HD + kc + 8];
            qh[ks][3] = *(const uint32*)&Qhb[(size_t)(row0 + 8) * HD + kc + 8];
            ql[ks][0] = *(const uint32*)&Qlb[(size_t)row0 * HD + kc];
            ql[ks][1] = *(const uint32*)&Qlb[(size_t)(row0 + 8) * HD + kc];
            ql[ks][2] = *(const uint32*)&Qlb[(size_t)row0 * HD + kc + 8];
            ql[ks][3] = *(const uint32*)&Qlb[(size_t)(row0 + 8) * HD + kc + 8];
        }
    }

    // ldmatrix lane-invariant offsets
    const uint32 kOffBase = (uint32)((((lane >> 4) << 3) + (lane & 7)) * 144
                                     + ((lane >> 3) & 1) * 16);
    const uint32 vOffBase = (uint32)(((lane & 7) + (((lane >> 3) & 1) << 3)) * 144
                                     + (lane >> 4) * 16);

    float o[8][4];
    #pragma unroll
    for (int t = 0; t < 8; t++)
        #pragma unroll
        for (int i = 0; i < 4; i++) o[t][i] = 0.f;
    float m0 = -INFINITY, m1 = -INFINITY, l0 = 0.f, l1 = 0.f;

    const __nv_bfloat16* kvsrc[4] = {Kh + headoff, Kl + headoff,
                                     Vh + headoff, Vl + headoff};
    const int ntiles = 2 * (qt + 1);

    // tile loader: 8 x cp16 per thread
    {
        #pragma unroll
        for (int t = 0; t < 8; t++) {
            int id = tid + t * 256;
            int arr = id >> 9;
            int r = (id >> 3) & 63;
            int c = id & 7;
            cp16(smem_u + (uint32)(arr * 9216 + r * 144 + c * 16),
                 kvsrc[arr] + (size_t)r * HD + c * 8);
        }
        cp_commit();
    }

    for (int tt = 0; tt < ntiles; tt++) {
        int kb = tt * 64;
        if (tt + 1 < ntiles) {
            uint32 stn = (uint32)((tt + 1) & 1) * 36864;
            int kbn = kb + 64;
            #pragma unroll
            for (int t = 0; t < 8; t++) {
                int id = tid + t * 256;
                int arr = id >> 9;
                int r = (id >> 3) & 63;
                int c = id & 7;
                cp16(smem_u + stn + (uint32)(arr * 9216 + r * 144 + c * 16),
                     kvsrc[arr] + (size_t)(kbn + r) * HD + c * 8);
            }
            cp_commit();
            cp_wait<1>();
        } else {
            cp_wait<0>();
        }
        __syncthreads();

        uint32 stb = smem_u + (uint32)(tt & 1) * 36864;
        uint32 khb = stb, klb = stb + 9216, vhb = stb + 18432, vlb = stb + 27648;

        // ---- S = Q K^T (3-term split) ----
        float s[8][4];
        #pragma unroll
        for (int t = 0; t < 8; t++)
            #pragma unroll
            for (int i = 0; i < 4; i++) s[t][i] = 0.f;

        #pragma unroll
        for (int ks = 0; ks < 4; ks++) {
            uint32 bh[4][4], bl[4][4];
            #pragma unroll
            for (int g = 0; g < 4; g++) {
                ldsm_x4(bh[g], khb + (uint32)(g * 2304 + ks * 32) + kOffBase);
                ldsm_x4(bl[g], klb + (uint32)(g * 2304 + ks * 32) + kOffBase);
            }
            #pragma unroll
            for (int g = 0; g < 4; g++) {
                mma_bf16(s[2*g],   qh[ks], bh[g][0], bh[g][1]);
                mma_bf16(s[2*g+1], qh[ks], bh[g][2], bh[g][3]);
            }
            #pragma unroll
            for (int g = 0; g < 4; g++) {
                mma_bf16(s[2*g],   qh[ks], bl[g][0], bl[g][1]);
                mma_bf16(s[2*g+1], qh[ks], bl[g][2], bl[g][3]);
            }
            #pragma unroll
            for (int g = 0; g < 4; g++) {
                mma_bf16(s[2*g],   ql[ks], bh[g][0], bh[g][1]);
                mma_bf16(s[2*g+1], ql[ks], bh[g][2], bh[g][3]);
            }
        }

        // ---- causal mask (diagonal tiles only) ----
        if (kb + 63 > q0 + wq * 16) {
            #pragma unroll
            for (int t = 0; t < 8; t++) {
                int key = kb + t * 8 + 2 * tig;
                if (key     > row0)     s[t][0] = -INFINITY;
                if (key + 1 > row0)     s[t][1] = -INFINITY;
                if (key     > row0 + 8) s[t][2] = -INFINITY;
                if (key + 1 > row0 + 8) s[t][3] = -INFINITY;
            }
        }

        // ---- online softmax ----
        float r0 = -INFINITY, r1 = -INFINITY;
        #pragma unroll
        for (int t = 0; t < 8; t++) {
            r0 = fmaxf(r0, fmaxf(s[t][0], s[t][1]));
            r1 = fmaxf(r1, fmaxf(s[t][2], s[t][3]));
        }
        r0 = fmaxf(r0, __shfl_xor_sync(0xffffffffu, r0, 1));
        r0 = fmaxf(r0, __shfl_xor_sync(0xffffffffu, r0, 2));
        r1 = fmaxf(r1, __shfl_xor_sync(0xffffffffu, r1, 1));
        r1 = fmaxf(r1, __shfl_xor_sync(0xffffffffu, r1, 2));
        float mn0 = fmaxf(m0, r0), mn1 = fmaxf(m1, r1);
        float c0 = __expf(m0 - mn0), c1 = __expf(m1 - mn1);
        m0 = mn0; m1 = mn1;
        l0 *= c0;  l1 *= c1;
        #pragma unroll
        for (int t = 0; t < 8; t++) {
            s[t][0] = __expf(s[t][0] - m0);
            s[t][1] = __expf(s[t][1] - m0);
            s[t][2] = __expf(s[t][2] - m1);
            s[t][3] = __expf(s[t][3] - m1);
            l0 += s[t][0] + s[t][1];
            l1 += s[t][2] + s[t][3];
        }
        #pragma unroll
        for (int t = 0; t < 8; t++) {
            o[t][0] *= c0; o[t][1] *= c0;
            o[t][2] *= c1; o[t][3] *= c1;
        }

        // ---- pack P (C-frag == A-frag identity), hi/lo split ----
        uint32 ph[4][4], pl[4][4];
        #pragma unroll
        for (int kk = 0; kk < 4; kk++) {
            split2(s[2*kk][0],   s[2*kk][1],   ph[kk][0], pl[kk][0]);
            split2(s[2*kk][2],   s[2*kk][3],   ph[kk][1], pl[kk][1]);
            split2(s[2*kk+1][0], s[2*kk+1][1], ph[kk][2], pl[kk][2]);
            split2(s[2*kk+1][2], s[2*kk+1][3], ph[kk][3], pl[kk][3]);
        }

        // ---- O += P V (3-term split) ----
        #pragma unroll
        for (int kk = 0; kk < 4; kk++) {
            uint32 vh4[4][4], vl4[4][4];
            #pragma unroll
            for (int g = 0; g < 4; g++) {
                ldsm_x4_t(vh4[g], vhb + (uint32)(kk * 2304 + g * 32) + vOffBase);
                ldsm_x4_t(vl4[g], vlb + (uint32)(kk * 2304 + g * 32) + vOffBase);
            }
            #pragma unroll
            for (int g = 0; g < 4; g++) {
                mma_bf16(o[2*g],   ph[kk], vh4[g][0], vh4[g][1]);
                mma_bf16(o[2*g+1], ph[kk], vh4[g][2], vh4[g][3]);
            }
            #pragma unroll
            for (int g = 0; g < 4; g++) {
                mma_bf16(o[2*g],   ph[kk], vl4[g][0], vl4[g][1]);
                mma_bf16(o[2*g+1], ph[kk], vl4[g][2], vl4[g][3]);
            }
            #pragma unroll
            for (int g = 0; g < 4; g++) {
                mma_bf16(o[2*g],   pl[kk], vh4[g][0], vh4[g][1]);
                mma_bf16(o[2*g+1], pl[kk], vh4[g][2], vh4[g][3]);
            }
        }
        __syncthreads();
    }

    // ---- finalize: reduce l across quad, normalize, split-store bf16 ----
    l0 += __shfl_xor_sync(0xffffffffu, l0, 1);
    l0 += __shfl_xor_sync(0xffffffffu, l0, 2);
    l1 += __shfl_xor_sync(0xffffffffu, l1, 1);
    l1 += __shfl_xor_sync(0xffffffffu, l1, 2);
    float i0 = 1.f / l0, i1 = 1.f / l1;
    #pragma unroll
    for (int t = 0; t < 8; t++) {
        int col = h * HD + t * 8 + 2 * tig;
        size_t d0 = ((size_t)(b * SEQ + row0)) * DMODEL + col;
        size_t d1 = ((size_t)(b * SEQ + row0 + 8)) * DMODEL + col;
        uint32 hi, lo;
        split2(o[t][0] * i0, o[t][1] * i0, hi, lo);
        *(uint32*)&Oh[d0] = hi;  *(uint32*)&Ol[d0] = lo;
        split2(o[t][2] * i1, o[t][3] * i1, hi, lo);
        *(uint32*)&Oh[d1] = hi;  *(uint32*)&Ol[d1] = lo;
    }
}

// ---------------------------------------------------------------------------
// Launch
// ---------------------------------------------------------------------------
extern "C" void kernel_launch(void* const* d_in, const int* in_sizes, int n_in,
                              void* d_out, int out_size)
{
    const float* hidden = (const float*)d_in[0];   // [B,S,D]
    const float* W_attn = (const float*)d_in[1];   // [D,3D]
    const float* b_attn = (const float*)d_in[2];   // [3D]
    const float* W_proj = (const float*)d_in[3];   // [D,D]
    const float* b_proj = (const float*)d_in[4];   // [D]
    float* out = (float*)d_out;                    // [B,S,D]

    __nv_bfloat16 *hid_h, *hid_l, *wa_h, *wa_l, *wp_h, *wp_l, *at_h, *at_l;
    __nv_bfloat16 *q_h, *q_l, *k_h, *k_l, *v_h, *v_l;
    cudaGetSymbolAddress((void**)&hid_h, g_hid_h);
    cudaGetSymbolAddress((void**)&hid_l, g_hid_l);
    cudaGetSymbolAddress((void**)&wa_h, g_wa_h);
    cudaGetSymbolAddress((void**)&wa_l, g_wa_l);
    cudaGetSymbolAddress((void**)&wp_h, g_wp_h);
    cudaGetSymbolAddress((void**)&wp_l, g_wp_l);
    cudaGetSymbolAddress((void**)&at_h, g_at_h);
    cudaGetSymbolAddress((void**)&at_l, g_at_l);
    cudaGetSymbolAddress((void**)&q_h, g_q_h);
    cudaGetSymbolAddress((void**)&q_l, g_q_l);
    cudaGetSymbolAddress((void**)&k_h, g_k_h);
    cudaGetSymbolAddress((void**)&k_l, g_k_l);
    cudaGetSymbolAddress((void**)&v_h, g_v_h);
    cudaGetSymbolAddress((void**)&v_l, g_v_l);

    cudaFuncSetAttribute(gemm_mma_kernel<0>,
                         cudaFuncAttributeMaxDynamicSharedMemorySize,
                         GEMM_SMEM_BYTES);
    cudaFuncSetAttribute(gemm_mma_kernel<1>,
                         cudaFuncAttributeMaxDynamicSharedMemorySize,
                         GEMM_SMEM_BYTES);
    cudaFuncSetAttribute(attn_mma_kernel,
                         cudaFuncAttributeMaxDynamicSharedMemorySize,
                         ATTN_SMEM_BYTES);

    const int M = BATCH * SEQ;   // 4096

    // 0) fp32 -> bf16 hi/lo splits of GEMM inputs
    {
        int n1 = M * DMODEL;
        split_kernel<<<n1 / 1024, 256>>>(hidden, hid_h, hid_l, n1);
        int n2 = DMODEL * 3 * DMODEL;
        split_kernel<<<n2 / 1024, 256>>>(W_attn, wa_h, wa_l, n2);
        int n3 = DMODEL * DMODEL;
        split_kernel<<<n3 / 1024, 256>>>(W_proj, wp_h, wp_l, n3);
    }
    // 1) QKV projection (tensor cores) -> fused head-major bf16 hi/lo split
    {
        dim3 grid(3 * DMODEL / 128, M / 128);  // (24, 32)
        gemm_mma_kernel<1><<<grid, 512, GEMM_SMEM_BYTES>>>(
            hid_h, hid_l, wa_h, wa_l, b_attn, nullptr,
            q_h, q_l, k_h, k_l, v_h, v_l, M, 3 * DMODEL, DMODEL);
    }
    // 2) causal attention (tensor cores) -> bf16 hi/lo output split
    {
        dim3 grid(SEQ / 128, NHEAD, BATCH);    // (16, 16, 2)
        attn_mma_kernel<<<grid, 256, ATTN_SMEM_BYTES>>>(
            q_h, q_l, k_h, k_l, v_h, v_l, at_h, at_l);
    }
    // 3) output projection (tensor cores) -> fp32 out
    {
        dim3 grid(DMODEL / 128, M / 128);      // (8, 32)
        gemm_mma_kernel<0><<<grid, 512, GEMM_SMEM_BYTES>>>(
            at_h, at_l, wp_h, wp_l, b_proj, out,
            nullptr, nullptr, nullptr, nullptr, nullptr, nullptr,
            M, DMODEL, DMODEL);
    }
}

// round 12
// speedup vs baseline: 1.6466x; 1.6466x over previous
#include <cuda_runtime.h>
#include <cuda_bf16.h>
#include <cuda_fp16.h>
#include <math.h>

// Problem constants (fixed by the reference)
#define BATCH 2
#define SEQ   2048
#define DMODEL 1024
#define NHEAD 16
#define HD    64          // head dim
#define QKV_ROW (3*DMODEL)

typedef unsigned int uint32;

// ---- mma / ldmatrix / cp.async wrappers -----------------------------------
__device__ __forceinline__ void ldsm_x4(uint32 r[4], uint32 addr) {
    asm volatile("ldmatrix.sync.aligned.m8n8.x4.shared.b16 {%0,%1,%2,%3}, [%4];"
                 : "=r"(r[0]), "=r"(r[1]), "=r"(r[2]), "=r"(r[3]) : "r"(addr));
}
__device__ __forceinline__ void ldsm_x4_t(uint32 r[4], uint32 addr) {
    asm volatile("ldmatrix.sync.aligned.m8n8.x4.trans.shared.b16 {%0,%1,%2,%3}, [%4];"
                 : "=r"(r[0]), "=r"(r[1]), "=r"(r[2]), "=r"(r[3]) : "r"(addr));
}
__device__ __forceinline__ void mma_bf16(float d[4], const uint32 a[4],
                                         uint32 b0, uint32 b1) {
    asm volatile(
        "mma.sync.aligned.m16n8k16.row.col.f32.bf16.bf16.f32 "
        "{%0,%1,%2,%3}, {%4,%5,%6,%7}, {%8,%9}, {%10,%11,%12,%13};"
        : "=f"(d[0]), "=f"(d[1]), "=f"(d[2]), "=f"(d[3])
        : "r"(a[0]), "r"(a[1]), "r"(a[2]), "r"(a[3]),
          "r"(b0), "r"(b1),
          "f"(d[0]), "f"(d[1]), "f"(d[2]), "f"(d[3]));
}
__device__ __forceinline__ void mma_f16(float d[4], const uint32 a[4],
                                        uint32 b0, uint32 b1) {
    asm volatile(
        "mma.sync.aligned.m16n8k16.row.col.f32.f16.f16.f32 "
        "{%0,%1,%2,%3}, {%4,%5,%6,%7}, {%8,%9}, {%10,%11,%12,%13};"
        : "=f"(d[0]), "=f"(d[1]), "=f"(d[2]), "=f"(d[3])
        : "r"(a[0]), "r"(a[1]), "r"(a[2]), "r"(a[3]),
          "r"(b0), "r"(b1),
          "f"(d[0]), "f"(d[1]), "f"(d[2]), "f"(d[3]));
}
__device__ __forceinline__ void cp16(uint32 smem_addr, const void* gptr) {
    asm volatile("cp.async.ca.shared.global [%0], [%1], 16;\n"
                 :: "r"(smem_addr), "l"(gptr));
}
__device__ __forceinline__ void cp_commit() {
    asm volatile("cp.async.commit_group;\n");
}
template<int N> __device__ __forceinline__ void cp_wait() {
    asm volatile("cp.async.wait_group %0;\n" :: "n"(N));
}

// split one float pair -> packed bf16x2 hi + packed bf16x2 lo
__device__ __forceinline__ void split2(float x, float y, uint32 &hi, uint32 &lo) {
    __nv_bfloat162 h2 = __floats2bfloat162_rn(x, y);
    hi = *reinterpret_cast<uint32*>(&h2);
    float rx = x - __bfloat162float(h2.x);
    float ry = y - __bfloat162float(h2.y);
    __nv_bfloat162 l2 = __floats2bfloat162_rn(rx, ry);
    lo = *reinterpret_cast<uint32*>(&l2);
}

// Scratch (allocation-free rule: __device__ globals)
__device__ __half g_h16[(size_t)BATCH*SEQ*DMODEL];        // fp16 hidden
__device__ __half g_wa16[(size_t)DMODEL*3*DMODEL];        // fp16 W_attn
__device__ __half g_wp16[(size_t)DMODEL*DMODEL];          // fp16 W_proj
__device__ __half g_at16[(size_t)BATCH*SEQ*DMODEL];       // fp16 attn out
// head-major [B][H][S][HD] bf16 splits of q (pre-scaled by 1/8), k, v
#define HEADS_ELEMS ((size_t)BATCH*NHEAD*SEQ*HD)
__device__ __nv_bfloat16 g_q_h[HEADS_ELEMS];
__device__ __nv_bfloat16 g_q_l[HEADS_ELEMS];
__device__ __nv_bfloat16 g_k_h[HEADS_ELEMS];
__device__ __nv_bfloat16 g_k_l[HEADS_ELEMS];
__device__ __nv_bfloat16 g_v_h[HEADS_ELEMS];
__device__ __nv_bfloat16 g_v_l[HEADS_ELEMS];

// ---------------------------------------------------------------------------
// fp32 -> fp16 convert
// ---------------------------------------------------------------------------
__global__ __launch_bounds__(256)
void conv_kernel(const float* __restrict__ x, __half* __restrict__ y, int n)
{
    int i = (blockIdx.x * 256 + threadIdx.x) * 4;
    if (i >= n) return;
    float4 v = *(const float4*)&x[i];
    *(__half2*)&y[i]     = __floats2half2_rn(v.x, v.y);
    *(__half2*)&y[i + 2] = __floats2half2_rn(v.z, v.w);
}

// ---------------------------------------------------------------------------
// Tensor-core fp16 GEMM (single term, fp32 accumulate), cp.async double
// buffered.  C[M,N] = A[M,K] @ W[K,N] + bias.
// BM=128, BN=128, BK=32, 256 threads / 8 warps (4m x 2n), warp tile 32x64.
// MODE 0: bias + fp32 store.  MODE 1: bias, q-scale, bf16 hi/lo split,
// head-major scatter to Q/K/V (N = 3*DMODEL).
// smem: A [2][128][5 chunks] @0 (stage stride 10240 B),
//       W [2][32][17 chunks] @20480 (stage stride 8704 B); total 37888 B.
// ---------------------------------------------------------------------------
#define GEMM_SMEM_BYTES 37888
template<int MODE>
__global__ __launch_bounds__(256, 2)
void gemm_fp16_kernel(const __half* __restrict__ A,
                      const __half* __restrict__ W,
                      const float* __restrict__ bias,
                      float* __restrict__ C,
                      __nv_bfloat16* __restrict__ Qh, __nv_bfloat16* __restrict__ Ql,
                      __nv_bfloat16* __restrict__ Kh, __nv_bfloat16* __restrict__ Kl,
                      __nv_bfloat16* __restrict__ Vh, __nv_bfloat16* __restrict__ Vl,
                      int M, int N, int K)
{
    extern __shared__ uint4 dsm[];
    uint32 base = (uint32)__cvta_generic_to_shared(dsm);
    const uint32 oA = 0, oW = 20480;
    const uint32 stA = 10240, stW = 8704;

    const int tid  = threadIdx.x;
    const int lane = tid & 31;
    const int wid  = tid >> 5;
    const int warp_m = wid & 3;
    const int warp_n = wid >> 2;
    const int row0 = blockIdx.y * 128;
    const int col0 = blockIdx.x * 128;

    // ldmatrix lane offsets
    const int j  = lane & 7;
    const int q  = lane >> 3;
    const int a_row_off = j + (q & 1) * 8;
    const int a_chk_off = q >> 1;
    uint32 aOff[2];
    #pragma unroll
    for (int ma = 0; ma < 2; ma++) {
        int r = warp_m * 32 + ma * 16 + a_row_off;
        aOff[ma] = (uint32)(r * 5 + a_chk_off) * 16;
    }
    uint32 wOff[4];
    #pragma unroll
    for (int nb = 0; nb < 4; nb++) {
        int k = j + (q & 1) * 8;
        int chk = (warp_n * 64 + nb * 16) / 8 + (q >> 1);
        wOff[nb] = (uint32)(k * 17 + chk) * 16;
    }

    // loader coordinates: 2 chunks per array per thread
    int aR[2], aC[2], wR[2], wC[2];
    #pragma unroll
    for (int t = 0; t < 2; t++) {
        int id = tid + t * 256;
        aR[t] = id >> 2;  aC[t] = id & 3;
        wR[t] = id >> 4;  wC[t] = id & 15;
    }

    float acc[2][8][4];
    #pragma unroll
    for (int ma = 0; ma < 2; ma++)
        #pragma unroll
        for (int na = 0; na < 8; na++)
            #pragma unroll
            for (int i = 0; i < 4; i++)
                acc[ma][na][i] = 0.f;

    const int nkt = K / 32;
    // prologue: stage 0
    #pragma unroll
    for (int t = 0; t < 2; t++) {
        cp16(base + oA + (uint32)(aR[t] * 5 + aC[t]) * 16,
             &A[(size_t)(row0 + aR[t]) * K + aC[t] * 8]);
        cp16(base + oW + (uint32)(wR[t] * 17 + wC[t]) * 16,
             &W[(size_t)(wR[t]) * N + col0 + wC[t] * 8]);
    }
    cp_commit();

    for (int kt = 0; kt < nkt; kt++) {
        if (kt + 1 < nkt) {
            uint32 st = (uint32)((kt + 1) & 1);
            int k0n = (kt + 1) * 32;
            #pragma unroll
            for (int t = 0; t < 2; t++) {
                cp16(base + oA + st * stA + (uint32)(aR[t] * 5 + aC[t]) * 16,
                     &A[(size_t)(row0 + aR[t]) * K + k0n + aC[t] * 8]);
                cp16(base + oW + st * stW + (uint32)(wR[t] * 17 + wC[t]) * 16,
                     &W[(size_t)(k0n + wR[t]) * N + col0 + wC[t] * 8]);
            }
            cp_commit();
            cp_wait<1>();
        } else {
            cp_wait<0>();
        }
        __syncthreads();

        uint32 st = (uint32)(kt & 1);
        uint32 bA = base + oA + st * stA;
        uint32 bW = base + oW + st * stW;

        #pragma unroll
        for (int ks = 0; ks < 2; ks++) {
            uint32 af[2][4], bf[4][4];
            ldsm_x4(af[0], bA + aOff[0] + ks * 32);
            ldsm_x4(af[1], bA + aOff[1] + ks * 32);
            #pragma unroll
            for (int nb = 0; nb < 4; nb++)
                ldsm_x4_t(bf[nb], bW + wOff[nb] + ks * 4352);  // +16 k * 272B
            #pragma unroll
            for (int nb = 0; nb < 4; nb++)
                #pragma unroll
                for (int ma = 0; ma < 2; ma++) {
                    mma_f16(acc[ma][2*nb],   af[ma], bf[nb][0], bf[nb][1]);
                    mma_f16(acc[ma][2*nb+1], af[ma], bf[nb][2], bf[nb][3]);
                }
        }
        __syncthreads();
    }

    // ---- epilogue ----
    int r_base = row0 + warp_m * 32 + (lane >> 2);
    int c_base = col0 + warp_n * 64 + (lane & 3) * 2;
    #pragma unroll
    for (int ma = 0; ma < 2; ma++) {
        #pragma unroll
        for (int na = 0; na < 8; na++) {
            int c = c_base + na * 8;
            float bx = bias[c], by = bias[c + 1];
            #pragma unroll
            for (int half_i = 0; half_i < 2; half_i++) {
                int r = r_base + ma * 16 + half_i * 8;
                float vx = acc[ma][na][2 * half_i + 0] + bx;
                float vy = acc[ma][na][2 * half_i + 1] + by;
                if (MODE == 0) {
                    *(float2*)&C[(size_t)r * N + c] = make_float2(vx, vy);
                } else {
                    int arr = c >> 10;               // 0=q 1=k 2=v
                    int hh  = (c >> 6) & 15;
                    int dd  = c & 63;
                    int bb  = r >> 11, ss = r & 2047;
                    size_t dst = (((size_t)(bb * NHEAD + hh)) * SEQ + ss) * HD + dd;
                    if (arr == 0) { vx *= 0.125f; vy *= 0.125f; }
                    uint32 hi, lo;
                    split2(vx, vy, hi, lo);
                    __nv_bfloat16* ph = (arr == 0) ? Qh : (arr == 1) ? Kh : Vh;
                    __nv_bfloat16* pl = (arr == 0) ? Ql : (arr == 1) ? Kl : Vl;
                    *(uint32*)&ph[dst] = hi;
                    *(uint32*)&pl[dst] = lo;
                }
            }
        }
    }
}

// ---------------------------------------------------------------------------
// MMA causal flash attention (bf16 3-term splits, fp32 softmax/accum);
// epilogue writes a single fp16 array (proj GEMM input).
// BM=128 q rows/block, BN=64 keys/tile, 8 warps (warp = 16 q rows).
// ---------------------------------------------------------------------------
#define ATTN_SMEM_BYTES (2 * 36864)
__global__ __launch_bounds__(256, 1)
void attn_mma_kernel(const __nv_bfloat16* __restrict__ Qh,
                     const __nv_bfloat16* __restrict__ Ql,
                     const __nv_bfloat16* __restrict__ Kh,
                     const __nv_bfloat16* __restrict__ Kl,
                     const __nv_bfloat16* __restrict__ Vh,
                     const __nv_bfloat16* __restrict__ Vl,
                     __half* __restrict__ O16)
{
    extern __shared__ uint4 dsm[];
    uint32 smem_u = (uint32)__cvta_generic_to_shared(dsm);

    const int tid  = threadIdx.x;
    const int lane = tid & 31;
    const int wq   = tid >> 5;
    const int qt = (int)gridDim.x - 1 - (int)blockIdx.x;
    const int h = blockIdx.y, b = blockIdx.z;
    const int q0 = qt * 128;
    const size_t headoff = ((size_t)(b * NHEAD + h)) * SEQ * HD;

    const int gid = lane >> 2;
    const int tig = lane & 3;
    const int row0 = q0 + wq * 16 + gid;

    uint32 qh[4][4], ql[4][4];
    {
        const __nv_bfloat16* Qhb = Qh + headoff;
        const __nv_bfloat16* Qlb = Ql + headoff;
        #pragma unroll
        for (int ks = 0; ks < 4; ks++) {
            int kc = ks * 16 + 2 * tig;
            qh[ks][0] = *(const uint32*)&Qhb[(size_t)row0 * HD + kc];
            qh[ks][1] = *(const uint32*)&Qhb[(size_t)(row0 + 8) * HD + kc];
            qh[ks][2] = *(const uint32*)&Qhb[(size_t)row0 * HD + kc + 8];
            qh[ks][3] = *(const uint32*)&Qhb[(size_t)(row0 + 8) * HD + kc + 8];
            ql[ks][0] = *(const uint32*)&Qlb[(size_t)row0 * HD + kc];
            ql[ks][1] = *(const uint32*)&Qlb[(size_t)(row0 + 8) * HD + kc];
            ql[ks][2] = *(const uint32*)&Qlb[(size_t)row0 * HD + kc + 8];
            ql[ks][3] = *(const uint32*)&Qlb[(size_t)(row0 + 8) * HD + kc + 8];
        }
    }

    const uint32 kOffBase = (uint32)((((lane >> 4) << 3) + (lane & 7)) * 144
                                     + ((lane >> 3) & 1) * 16);
    const uint32 vOffBase = (uint32)(((lane & 7) + (((lane >> 3) & 1) << 3)) * 144
                                     + (lane >> 4) * 16);

    float o[8][4];
    #pragma unroll
    for (int t = 0; t < 8; t++)
        #pragma unroll
        for (int i = 0; i < 4; i++) o[t][i] = 0.f;
    float m0 = -INFINITY, m1 = -INFINITY, l0 = 0.f, l1 = 0.f;

    const __nv_bfloat16* kvsrc[4] = {Kh + headoff, Kl + headoff,
                                     Vh + headoff, Vl + headoff};
    const int ntiles = 2 * (qt + 1);

    {
        #pragma unroll
        for (int t = 0; t < 8; t++) {
            int id = tid + t * 256;
            int arr = id >> 9;
            int r = (id >> 3) & 63;
            int c = id & 7;
            cp16(smem_u + (uint32)(arr * 9216 + r * 144 + c * 16),
                 kvsrc[arr] + (size_t)r * HD + c * 8);
        }
        cp_commit();
    }

    for (int tt = 0; tt < ntiles; tt++) {
        int kb = tt * 64;
        if (tt + 1 < ntiles) {
            uint32 stn = (uint32)((tt + 1) & 1) * 36864;
            int kbn = kb + 64;
            #pragma unroll
            for (int t = 0; t < 8; t++) {
                int id = tid + t * 256;
                int arr = id >> 9;
                int r = (id >> 3) & 63;
                int c = id & 7;
                cp16(smem_u + stn + (uint32)(arr * 9216 + r * 144 + c * 16),
                     kvsrc[arr] + (size_t)(kbn + r) * HD + c * 8);
            }
            cp_commit();
            cp_wait<1>();
        } else {
            cp_wait<0>();
        }
        __syncthreads();

        uint32 stb = smem_u + (uint32)(tt & 1) * 36864;
        uint32 khb = stb, klb = stb + 9216, vhb = stb + 18432, vlb = stb + 27648;

        float s[8][4];
        #pragma unroll
        for (int t = 0; t < 8; t++)
            #pragma unroll
            for (int i = 0; i < 4; i++) s[t][i] = 0.f;

        #pragma unroll
        for (int ks = 0; ks < 4; ks++) {
            uint32 bh[4][4], bl[4][4];
            #pragma unroll
            for (int g = 0; g < 4; g++) {
                ldsm_x4(bh[g], khb + (uint32)(g * 2304 + ks * 32) + kOffBase);
                ldsm_x4(bl[g], klb + (uint32)(g * 2304 + ks * 32) + kOffBase);
            }
            #pragma unroll
            for (int g = 0; g < 4; g++) {
                mma_bf16(s[2*g],   qh[ks], bh[g][0], bh[g][1]);
                mma_bf16(s[2*g+1], qh[ks], bh[g][2], bh[g][3]);
            }
            #pragma unroll
            for (int g = 0; g < 4; g++) {
                mma_bf16(s[2*g],   qh[ks], bl[g][0], bl[g][1]);
                mma_bf16(s[2*g+1], qh[ks], bl[g][2], bl[g][3]);
            }
            #pragma unroll
            for (int g = 0; g < 4; g++) {
                mma_bf16(s[2*g],   ql[ks], bh[g][0], bh[g][1]);
                mma_bf16(s[2*g+1], ql[ks], bh[g][2], bh[g][3]);
            }
        }

        if (kb + 63 > q0 + wq * 16) {
            #pragma unroll
            for (int t = 0; t < 8; t++) {
                int key = kb + t * 8 + 2 * tig;
                if (key     > row0)     s[t][0] = -INFINITY;
                if (key + 1 > row0)     s[t][1] = -INFINITY;
                if (key     > row0 + 8) s[t][2] = -INFINITY;
                if (key + 1 > row0 + 8) s[t][3] = -INFINITY;
            }
        }

        float r0 = -INFINITY, r1 = -INFINITY;
        #pragma unroll
        for (int t = 0; t < 8; t++) {
            r0 = fmaxf(r0, fmaxf(s[t][0], s[t][1]));
            r1 = fmaxf(r1, fmaxf(s[t][2], s[t][3]));
        }
        r0 = fmaxf(r0, __shfl_xor_sync(0xffffffffu, r0, 1));
        r0 = fmaxf(r0, __shfl_xor_sync(0xffffffffu, r0, 2));
        r1 = fmaxf(r1, __shfl_xor_sync(0xffffffffu, r1, 1));
        r1 = fmaxf(r1, __shfl_xor_sync(0xffffffffu, r1, 2));
        float mn0 = fmaxf(m0, r0), mn1 = fmaxf(m1, r1);
        float c0 = __expf(m0 - mn0), c1 = __expf(m1 - mn1);
        m0 = mn0; m1 = mn1;
        l0 *= c0;  l1 *= c1;
        #pragma unroll
        for (int t = 0; t < 8; t++) {
            s[t][0] = __expf(s[t][0] - m0);
            s[t][1] = __expf(s[t][1] - m0);
            s[t][2] = __expf(s[t][2] - m1);
            s[t][3] = __expf(s[t][3] - m1);
            l0 += s[t][0] + s[t][1];
            l1 += s[t][2] + s[t][3];
        }
        #pragma unroll
        for (int t = 0; t < 8; t++) {
            o[t][0] *= c0; o[t][1] *= c0;
            o[t][2] *= c1; o[t][3] *= c1;
        }

        uint32 ph[4][4], pl[4][4];
        #pragma unroll
        for (int kk = 0; kk < 4; kk++) {
            split2(s[2*kk][0],   s[2*kk][1],   ph[kk][0], pl[kk][0]);
            split2(s[2*kk][2],   s[2*kk][3],   ph[kk][1], pl[kk][1]);
            split2(s[2*kk+1][0], s[2*kk+1][1], ph[kk][2], pl[kk][2]);
            split2(s[2*kk+1][2], s[2*kk+1][3], ph[kk][3], pl[kk][3]);
        }

        #pragma unroll
        for (int kk = 0; kk < 4; kk++) {
            uint32 vh4[4][4], vl4[4][4];
            #pragma unroll
            for (int g = 0; g < 4; g++) {
                ldsm_x4_t(vh4[g], vhb + (uint32)(kk * 2304 + g * 32) + vOffBase);
                ldsm_x4_t(vl4[g], vlb + (uint32)(kk * 2304 + g * 32) + vOffBase);
            }
            #pragma unroll
            for (int g = 0; g < 4; g++) {
                mma_bf16(o[2*g],   ph[kk], vh4[g][0], vh4[g][1]);
                mma_bf16(o[2*g+1], ph[kk], vh4[g][2], vh4[g][3]);
            }
            #pragma unroll
            for (int g = 0; g < 4; g++) {
                mma_bf16(o[2*g],   ph[kk], vl4[g][0], vl4[g][1]);
                mma_bf16(o[2*g+1], ph[kk], vl4[g][2], vl4[g][3]);
            }
            #pragma unroll
            for (int g = 0; g < 4; g++) {
                mma_bf16(o[2*g],   pl[kk], vh4[g][0], vh4[g][1]);
                mma_bf16(o[2*g+1], pl[kk], vh4[g][2], vh4[g][3]);
            }
        }
        __syncthreads();
    }

    l0 += __shfl_xor_sync(0xffffffffu, l0, 1);
    l0 += __shfl_xor_sync(0xffffffffu, l0, 2);
    l1 += __shfl_xor_sync(0xffffffffu, l1, 1);
    l1 += __shfl_xor_sync(0xffffffffu, l1, 2);
    float i0 = 1.f / l0, i1 = 1.f / l1;
    #pragma unroll
    for (int t = 0; t < 8; t++) {
        int col = h * HD + t * 8 + 2 * tig;
        size_t d0 = ((size_t)(b * SEQ + row0)) * DMODEL + col;
        size_t d1 = ((size_t)(b * SEQ + row0 + 8)) * DMODEL + col;
        *(__half2*)&O16[d0] = __floats2half2_rn(o[t][0] * i0, o[t][1] * i0);
        *(__half2*)&O16[d1] = __floats2half2_rn(o[t][2] * i1, o[t][3] * i1);
    }
}

// ---------------------------------------------------------------------------
// Launch
// ---------------------------------------------------------------------------
extern "C" void kernel_launch(void* const* d_in, const int* in_sizes, int n_in,
                              void* d_out, int out_size)
{
    const float* hidden = (const float*)d_in[0];   // [B,S,D]
    const float* W_attn = (const float*)d_in[1];   // [D,3D]
    const float* b_attn = (const float*)d_in[2];   // [3D]
    const float* W_proj = (const float*)d_in[3];   // [D,D]
    const float* b_proj = (const float*)d_in[4];   // [D]
    float* out = (float*)d_out;                    // [B,S,D]

    __half *h16, *wa16, *wp16, *at16;
    __nv_bfloat16 *q_h, *q_l, *k_h, *k_l, *v_h, *v_l;
    cudaGetSymbolAddress((void**)&h16,  g_h16);
    cudaGetSymbolAddress((void**)&wa16, g_wa16);
    cudaGetSymbolAddress((void**)&wp16, g_wp16);
    cudaGetSymbolAddress((void**)&at16, g_at16);
    cudaGetSymbolAddress((void**)&q_h, g_q_h);
    cudaGetSymbolAddress((void**)&q_l, g_q_l);
    cudaGetSymbolAddress((void**)&k_h, g_k_h);
    cudaGetSymbolAddress((void**)&k_l, g_k_l);
    cudaGetSymbolAddress((void**)&v_h, g_v_h);
    cudaGetSymbolAddress((void**)&v_l, g_v_l);

    cudaFuncSetAttribute(gemm_fp16_kernel<0>,
                         cudaFuncAttributeMaxDynamicSharedMemorySize,
                         GEMM_SMEM_BYTES);
    cudaFuncSetAttribute(gemm_fp16_kernel<1>,
                         cudaFuncAttributeMaxDynamicSharedMemorySize,
                         GEMM_SMEM_BYTES);
    cudaFuncSetAttribute(attn_mma_kernel,
                         cudaFuncAttributeMaxDynamicSharedMemorySize,
                         ATTN_SMEM_BYTES);

    const int M = BATCH * SEQ;   // 4096

    // 0) fp32 -> fp16 converts
    {
        int n1 = M * DMODEL;
        conv_kernel<<<n1 / 1024, 256>>>(hidden, h16, n1);
        int n2 = DMODEL * 3 * DMODEL;
        conv_kernel<<<n2 / 1024, 256>>>(W_attn, wa16, n2);
        int n3 = DMODEL * DMODEL;
        conv_kernel<<<n3 / 1024, 256>>>(W_proj, wp16, n3);
    }
    // 1) QKV projection (fp16 mma) -> fused head-major bf16 hi/lo split
    {
        dim3 grid(3 * DMODEL / 128, M / 128);    // (24, 32)
        gemm_fp16_kernel<1><<<grid, 256, GEMM_SMEM_BYTES>>>(
            h16, wa16, b_attn, nullptr,
            q_h, q_l, k_h, k_l, v_h, v_l, M, 3 * DMODEL, DMODEL);
    }
    // 2) causal attention (bf16 3-term mma) -> fp16 output
    {
        dim3 grid(SEQ / 128, NHEAD, BATCH);      // (16, 16, 2)
        attn_mma_kernel<<<grid, 256, ATTN_SMEM_BYTES>>>(
            q_h, q_l, k_h, k_l, v_h, v_l, at16);
    }
    // 3) output projection (fp16 mma) -> fp32 out
    {
        dim3 grid(DMODEL / 128, M / 128);        // (8, 32)
        gemm_fp16_kernel<0><<<grid, 256, GEMM_SMEM_BYTES>>>(
            at16, wp16, b_proj, out,
            nullptr, nullptr, nullptr, nullptr, nullptr, nullptr,
            M, DMODEL, DMODEL);
    }
}

// round 13
// speedup vs baseline: 1.9641x; 1.1928x over previous
#include <cuda_runtime.h>
#include <cuda_bf16.h>
#include <cuda_fp16.h>
#include <math.h>

// Problem constants (fixed by the reference)
#define BATCH 2
#define SEQ   2048
#define DMODEL 1024
#define NHEAD 16
#define HD    64          // head dim
#define QKV_ROW (3*DMODEL)

typedef unsigned int uint32;

// ---- mma / ldmatrix / cp.async wrappers -----------------------------------
__device__ __forceinline__ void ldsm_x4(uint32 r[4], uint32 addr) {
    asm volatile("ldmatrix.sync.aligned.m8n8.x4.shared.b16 {%0,%1,%2,%3}, [%4];"
                 : "=r"(r[0]), "=r"(r[1]), "=r"(r[2]), "=r"(r[3]) : "r"(addr));
}
__device__ __forceinline__ void ldsm_x4_t(uint32 r[4], uint32 addr) {
    asm volatile("ldmatrix.sync.aligned.m8n8.x4.trans.shared.b16 {%0,%1,%2,%3}, [%4];"
                 : "=r"(r[0]), "=r"(r[1]), "=r"(r[2]), "=r"(r[3]) : "r"(addr));
}
__device__ __forceinline__ void mma_bf16(float d[4], const uint32 a[4],
                                         uint32 b0, uint32 b1) {
    asm volatile(
        "mma.sync.aligned.m16n8k16.row.col.f32.bf16.bf16.f32 "
        "{%0,%1,%2,%3}, {%4,%5,%6,%7}, {%8,%9}, {%10,%11,%12,%13};"
        : "=f"(d[0]), "=f"(d[1]), "=f"(d[2]), "=f"(d[3])
        : "r"(a[0]), "r"(a[1]), "r"(a[2]), "r"(a[3]),
          "r"(b0), "r"(b1),
          "f"(d[0]), "f"(d[1]), "f"(d[2]), "f"(d[3]));
}
__device__ __forceinline__ void mma_f16(float d[4], const uint32 a[4],
                                        uint32 b0, uint32 b1) {
    asm volatile(
        "mma.sync.aligned.m16n8k16.row.col.f32.f16.f16.f32 "
        "{%0,%1,%2,%3}, {%4,%5,%6,%7}, {%8,%9}, {%10,%11,%12,%13};"
        : "=f"(d[0]), "=f"(d[1]), "=f"(d[2]), "=f"(d[3])
        : "r"(a[0]), "r"(a[1]), "r"(a[2]), "r"(a[3]),
          "r"(b0), "r"(b1),
          "f"(d[0]), "f"(d[1]), "f"(d[2]), "f"(d[3]));
}
__device__ __forceinline__ void cp16(uint32 smem_addr, const void* gptr) {
    asm volatile("cp.async.ca.shared.global [%0], [%1], 16;\n"
                 :: "r"(smem_addr), "l"(gptr));
}
__device__ __forceinline__ void cp_commit() {
    asm volatile("cp.async.commit_group;\n");
}
template<int N> __device__ __forceinline__ void cp_wait() {
    asm volatile("cp.async.wait_group %0;\n" :: "n"(N));
}

// split one float pair -> packed bf16x2 hi + packed bf16x2 lo
__device__ __forceinline__ void split2(float x, float y, uint32 &hi, uint32 &lo) {
    __nv_bfloat162 h2 = __floats2bfloat162_rn(x, y);
    hi = *reinterpret_cast<uint32*>(&h2);
    float rx = x - __bfloat162float(h2.x);
    float ry = y - __bfloat162float(h2.y);
    __nv_bfloat162 l2 = __floats2bfloat162_rn(rx, ry);
    lo = *reinterpret_cast<uint32*>(&l2);
}
__device__ __forceinline__ uint32 pack_h2(float x, float y) {
    __half2 h = __floats2half2_rn(x, y);
    return *reinterpret_cast<uint32*>(&h);
}

// Scratch (allocation-free rule: __device__ globals)
__device__ __half g_h16[(size_t)BATCH*SEQ*DMODEL];        // fp16 hidden
__device__ __half g_wa16[(size_t)DMODEL*3*DMODEL];        // fp16 W_attn
__device__ __half g_wp16[(size_t)DMODEL*DMODEL];          // fp16 W_proj
__device__ __half g_at16[(size_t)BATCH*SEQ*DMODEL];       // fp16 attn out
// head-major [B][H][S][HD]: q/k bf16 hi+lo (q pre-scaled 1/8), v fp16
#define HEADS_ELEMS ((size_t)BATCH*NHEAD*SEQ*HD)
__device__ __nv_bfloat16 g_q_h[HEADS_ELEMS];
__device__ __nv_bfloat16 g_q_l[HEADS_ELEMS];
__device__ __nv_bfloat16 g_k_h[HEADS_ELEMS];
__device__ __nv_bfloat16 g_k_l[HEADS_ELEMS];
__device__ __half        g_v16[HEADS_ELEMS];

// ---------------------------------------------------------------------------
// fp32 -> fp16 convert
// ---------------------------------------------------------------------------
__global__ __launch_bounds__(256)
void conv_kernel(const float* __restrict__ x, __half* __restrict__ y, int n)
{
    int i = (blockIdx.x * 256 + threadIdx.x) * 4;
    if (i >= n) return;
    float4 v = *(const float4*)&x[i];
    *(__half2*)&y[i]     = __floats2half2_rn(v.x, v.y);
    *(__half2*)&y[i + 2] = __floats2half2_rn(v.z, v.w);
}

// ---------------------------------------------------------------------------
// Tensor-core fp16 GEMM (single term, fp32 accumulate), cp.async double
// buffered.  C[M,N] = A[M,K] @ W[K,N] + bias.
// BM=128, BN=128, BK=32, 256 threads / 8 warps (4m x 2n), warp tile 32x64.
// MODE 0: bias + fp32 store.  MODE 1: bias; q,k -> scale/split bf16 hi/lo,
// v -> fp16; head-major scatter (N = 3*DMODEL).
// ---------------------------------------------------------------------------
#define GEMM_SMEM_BYTES 37888
template<int MODE>
__global__ __launch_bounds__(256, 2)
void gemm_fp16_kernel(const __half* __restrict__ A,
                      const __half* __restrict__ W,
                      const float* __restrict__ bias,
                      float* __restrict__ C,
                      __nv_bfloat16* __restrict__ Qh, __nv_bfloat16* __restrict__ Ql,
                      __nv_bfloat16* __restrict__ Kh, __nv_bfloat16* __restrict__ Kl,
                      __half* __restrict__ V16,
                      int M, int N, int K)
{
    extern __shared__ uint4 dsm[];
    uint32 base = (uint32)__cvta_generic_to_shared(dsm);
    const uint32 oA = 0, oW = 20480;
    const uint32 stA = 10240, stW = 8704;

    const int tid  = threadIdx.x;
    const int lane = tid & 31;
    const int wid  = tid >> 5;
    const int warp_m = wid & 3;
    const int warp_n = wid >> 2;
    const int row0 = blockIdx.y * 128;
    const int col0 = blockIdx.x * 128;

    // ldmatrix lane offsets
    const int j  = lane & 7;
    const int q  = lane >> 3;
    const int a_row_off = j + (q & 1) * 8;
    const int a_chk_off = q >> 1;
    uint32 aOff[2];
    #pragma unroll
    for (int ma = 0; ma < 2; ma++) {
        int r = warp_m * 32 + ma * 16 + a_row_off;
        aOff[ma] = (uint32)(r * 5 + a_chk_off) * 16;
    }
    uint32 wOff[4];
    #pragma unroll
    for (int nb = 0; nb < 4; nb++) {
        int k = j + (q & 1) * 8;
        int chk = (warp_n * 64 + nb * 16) / 8 + (q >> 1);
        wOff[nb] = (uint32)(k * 17 + chk) * 16;
    }

    // loader coordinates: 2 chunks per array per thread
    int aR[2], aC[2], wR[2], wC[2];
    #pragma unroll
    for (int t = 0; t < 2; t++) {
        int id = tid + t * 256;
        aR[t] = id >> 2;  aC[t] = id & 3;
        wR[t] = id >> 4;  wC[t] = id & 15;
    }

    float acc[2][8][4];
    #pragma unroll
    for (int ma = 0; ma < 2; ma++)
        #pragma unroll
        for (int na = 0; na < 8; na++)
            #pragma unroll
            for (int i = 0; i < 4; i++)
                acc[ma][na][i] = 0.f;

    const int nkt = K / 32;
    // prologue: stage 0
    #pragma unroll
    for (int t = 0; t < 2; t++) {
        cp16(base + oA + (uint32)(aR[t] * 5 + aC[t]) * 16,
             &A[(size_t)(row0 + aR[t]) * K + aC[t] * 8]);
        cp16(base + oW + (uint32)(wR[t] * 17 + wC[t]) * 16,
             &W[(size_t)(wR[t]) * N + col0 + wC[t] * 8]);
    }
    cp_commit();

    for (int kt = 0; kt < nkt; kt++) {
        if (kt + 1 < nkt) {
            uint32 st = (uint32)((kt + 1) & 1);
            int k0n = (kt + 1) * 32;
            #pragma unroll
            for (int t = 0; t < 2; t++) {
                cp16(base + oA + st * stA + (uint32)(aR[t] * 5 + aC[t]) * 16,
                     &A[(size_t)(row0 + aR[t]) * K + k0n + aC[t] * 8]);
                cp16(base + oW + st * stW + (uint32)(wR[t] * 17 + wC[t]) * 16,
                     &W[(size_t)(k0n + wR[t]) * N + col0 + wC[t] * 8]);
            }
            cp_commit();
            cp_wait<1>();
        } else {
            cp_wait<0>();
        }
        __syncthreads();

        uint32 st = (uint32)(kt & 1);
        uint32 bA = base + oA + st * stA;
        uint32 bW = base + oW + st * stW;

        #pragma unroll
        for (int ks = 0; ks < 2; ks++) {
            uint32 af[2][4], bf[4][4];
            ldsm_x4(af[0], bA + aOff[0] + ks * 32);
            ldsm_x4(af[1], bA + aOff[1] + ks * 32);
            #pragma unroll
            for (int nb = 0; nb < 4; nb++)
                ldsm_x4_t(bf[nb], bW + wOff[nb] + ks * 4352);  // +16 k * 272B
            #pragma unroll
            for (int nb = 0; nb < 4; nb++)
                #pragma unroll
                for (int ma = 0; ma < 2; ma++) {
                    mma_f16(acc[ma][2*nb],   af[ma], bf[nb][0], bf[nb][1]);
                    mma_f16(acc[ma][2*nb+1], af[ma], bf[nb][2], bf[nb][3]);
                }
        }
        __syncthreads();
    }

    // ---- epilogue ----
    int r_base = row0 + warp_m * 32 + (lane >> 2);
    int c_base = col0 + warp_n * 64 + (lane & 3) * 2;
    #pragma unroll
    for (int ma = 0; ma < 2; ma++) {
        #pragma unroll
        for (int na = 0; na < 8; na++) {
            int c = c_base + na * 8;
            float bx = bias[c], by = bias[c + 1];
            #pragma unroll
            for (int half_i = 0; half_i < 2; half_i++) {
                int r = r_base + ma * 16 + half_i * 8;
                float vx = acc[ma][na][2 * half_i + 0] + bx;
                float vy = acc[ma][na][2 * half_i + 1] + by;
                if (MODE == 0) {
                    *(float2*)&C[(size_t)r * N + c] = make_float2(vx, vy);
                } else {
                    int arr = c >> 10;               // 0=q 1=k 2=v
                    int hh  = (c >> 6) & 15;
                    int dd  = c & 63;
                    int bb  = r >> 11, ss = r & 2047;
                    size_t dst = (((size_t)(bb * NHEAD + hh)) * SEQ + ss) * HD + dd;
                    if (arr == 2) {
                        *(__half2*)&V16[dst] = __floats2half2_rn(vx, vy);
                    } else {
                        if (arr == 0) { vx *= 0.125f; vy *= 0.125f; }
                        uint32 hi, lo;
                        split2(vx, vy, hi, lo);
                        __nv_bfloat16* ph = (arr == 0) ? Qh : Kh;
                        __nv_bfloat16* pl = (arr == 0) ? Ql : Kl;
                        *(uint32*)&ph[dst] = hi;
                        *(uint32*)&pl[dst] = lo;
                    }
                }
            }
        }
    }
}

// ---------------------------------------------------------------------------
// MMA causal flash attention.
// QK: bf16 3-term split (score precision).  PV: single-term fp16.
// fp32 softmax/accumulators.  Epilogue writes fp16 (proj GEMM input).
// BM=128 q rows/block, BN=64 keys/tile, 8 warps (warp = 16 q rows).
// smem per stage: Kh[64][72]bf16, Kl, V16[64][72]fp16 (9216 B each, rows
// 144 B padded); stage stride 27648 B, double buffered.
// ---------------------------------------------------------------------------
#define ATTN_SMEM_BYTES (2 * 27648)
__global__ __launch_bounds__(256, 1)
void attn_mma_kernel(const __nv_bfloat16* __restrict__ Qh,
                     const __nv_bfloat16* __restrict__ Ql,
                     const __nv_bfloat16* __restrict__ Kh,
                     const __nv_bfloat16* __restrict__ Kl,
                     const __half* __restrict__ V16,
                     __half* __restrict__ O16)
{
    extern __shared__ uint4 dsm[];
    uint32 smem_u = (uint32)__cvta_generic_to_shared(dsm);

    const int tid  = threadIdx.x;
    const int lane = tid & 31;
    const int wq   = tid >> 5;
    const int qt = (int)gridDim.x - 1 - (int)blockIdx.x;
    const int h = blockIdx.y, b = blockIdx.z;
    const int q0 = qt * 128;
    const size_t headoff = ((size_t)(b * NHEAD + h)) * SEQ * HD;

    const int gid = lane >> 2;
    const int tig = lane & 3;
    const int row0 = q0 + wq * 16 + gid;

    uint32 qh[4][4], ql[4][4];
    {
        const __nv_bfloat16* Qhb = Qh + headoff;
        const __nv_bfloat16* Qlb = Ql + headoff;
        #pragma unroll
        for (int ks = 0; ks < 4; ks++) {
            int kc = ks * 16 + 2 * tig;
            qh[ks][0] = *(const uint32*)&Qhb[(size_t)row0 * HD + kc];
            qh[ks][1] = *(const uint32*)&Qhb[(size_t)(row0 + 8) * HD + kc];
            qh[ks][2] = *(const uint32*)&Qhb[(size_t)row0 * HD + kc + 8];
            qh[ks][3] = *(const uint32*)&Qhb[(size_t)(row0 + 8) * HD + kc + 8];
            ql[ks][0] = *(const uint32*)&Qlb[(size_t)row0 * HD + kc];
            ql[ks][1] = *(const uint32*)&Qlb[(size_t)(row0 + 8) * HD + kc];
            ql[ks][2] = *(const uint32*)&Qlb[(size_t)row0 * HD + kc + 8];
            ql[ks][3] = *(const uint32*)&Qlb[(size_t)(row0 + 8) * HD + kc + 8];
        }
    }

    const uint32 kOffBase = (uint32)((((lane >> 4) << 3) + (lane & 7)) * 144
                                     + ((lane >> 3) & 1) * 16);
    const uint32 vOffBase = (uint32)(((lane & 7) + (((lane >> 3) & 1) << 3)) * 144
                                     + (lane >> 4) * 16);

    float o[8][4];
    #pragma unroll
    for (int t = 0; t < 8; t++)
        #pragma unroll
        for (int i = 0; i < 4; i++) o[t][i] = 0.f;
    float m0 = -INFINITY, m1 = -INFINITY, l0 = 0.f, l1 = 0.f;

    const void* kvsrc[3] = {Kh + headoff, Kl + headoff, V16 + headoff};
    const int ntiles = 2 * (qt + 1);

    // tile loader: 3 arrays x 64 rows x 8 chunks = 1536 chunks, 6/thread
    {
        #pragma unroll
        for (int t = 0; t < 6; t++) {
            int id = tid + t * 256;
            int arr = id >> 9;
            int r = (id >> 3) & 63;
            int c = id & 7;
            cp16(smem_u + (uint32)(arr * 9216 + r * 144 + c * 16),
                 (const char*)kvsrc[arr] + ((size_t)r * HD + c * 8) * 2);
        }
        cp_commit();
    }

    for (int tt = 0; tt < ntiles; tt++) {
        int kb = tt * 64;
        if (tt + 1 < ntiles) {
            uint32 stn = (uint32)((tt + 1) & 1) * 27648;
            int kbn = kb + 64;
            #pragma unroll
            for (int t = 0; t < 6; t++) {
                int id = tid + t * 256;
                int arr = id >> 9;
                int r = (id >> 3) & 63;
                int c = id & 7;
                cp16(smem_u + stn + (uint32)(arr * 9216 + r * 144 + c * 16),
                     (const char*)kvsrc[arr] + ((size_t)(kbn + r) * HD + c * 8) * 2);
            }
            cp_commit();
            cp_wait<1>();
        } else {
            cp_wait<0>();
        }
        __syncthreads();

        uint32 stb = smem_u + (uint32)(tt & 1) * 27648;
        uint32 khb = stb, klb = stb + 9216, vb = stb + 18432;

        // ---- S = Q K^T (3-term bf16 split) ----
        float s[8][4];
        #pragma unroll
        for (int t = 0; t < 8; t++)
            #pragma unroll
            for (int i = 0; i < 4; i++) s[t][i] = 0.f;

        #pragma unroll
        for (int ks = 0; ks < 4; ks++) {
            uint32 bh[4][4], bl[4][4];
            #pragma unroll
            for (int g = 0; g < 4; g++) {
                ldsm_x4(bh[g], khb + (uint32)(g * 2304 + ks * 32) + kOffBase);
                ldsm_x4(bl[g], klb + (uint32)(g * 2304 + ks * 32) + kOffBase);
            }
            #pragma unroll
            for (int g = 0; g < 4; g++) {
                mma_bf16(s[2*g],   qh[ks], bh[g][0], bh[g][1]);
                mma_bf16(s[2*g+1], qh[ks], bh[g][2], bh[g][3]);
            }
            #pragma unroll
            for (int g = 0; g < 4; g++) {
                mma_bf16(s[2*g],   qh[ks], bl[g][0], bl[g][1]);
                mma_bf16(s[2*g+1], qh[ks], bl[g][2], bl[g][3]);
            }
            #pragma unroll
            for (int g = 0; g < 4; g++) {
                mma_bf16(s[2*g],   ql[ks], bh[g][0], bh[g][1]);
                mma_bf16(s[2*g+1], ql[ks], bh[g][2], bh[g][3]);
            }
        }

        // ---- causal mask (diagonal tiles only) ----
        if (kb + 63 > q0 + wq * 16) {
            #pragma unroll
            for (int t = 0; t < 8; t++) {
                int key = kb + t * 8 + 2 * tig;
                if (key     > row0)     s[t][0] = -INFINITY;
                if (key + 1 > row0)     s[t][1] = -INFINITY;
                if (key     > row0 + 8) s[t][2] = -INFINITY;
                if (key + 1 > row0 + 8) s[t][3] = -INFINITY;
            }
        }

        // ---- online softmax ----
        float r0 = -INFINITY, r1 = -INFINITY;
        #pragma unroll
        for (int t = 0; t < 8; t++) {
            r0 = fmaxf(r0, fmaxf(s[t][0], s[t][1]));
            r1 = fmaxf(r1, fmaxf(s[t][2], s[t][3]));
        }
        r0 = fmaxf(r0, __shfl_xor_sync(0xffffffffu, r0, 1));
        r0 = fmaxf(r0, __shfl_xor_sync(0xffffffffu, r0, 2));
        r1 = fmaxf(r1, __shfl_xor_sync(0xffffffffu, r1, 1));
        r1 = fmaxf(r1, __shfl_xor_sync(0xffffffffu, r1, 2));
        float mn0 = fmaxf(m0, r0), mn1 = fmaxf(m1, r1);
        float c0 = __expf(m0 - mn0), c1 = __expf(m1 - mn1);
        m0 = mn0; m1 = mn1;
        l0 *= c0;  l1 *= c1;
        #pragma unroll
        for (int t = 0; t < 8; t++) {
            s[t][0] = __expf(s[t][0] - m0);
            s[t][1] = __expf(s[t][1] - m0);
            s[t][2] = __expf(s[t][2] - m1);
            s[t][3] = __expf(s[t][3] - m1);
            l0 += s[t][0] + s[t][1];
            l1 += s[t][2] + s[t][3];
        }
        #pragma unroll
        for (int t = 0; t < 8; t++) {
            o[t][0] *= c0; o[t][1] *= c0;
            o[t][2] *= c1; o[t][3] *= c1;
        }

        // ---- pack P fp16 (C-frag == A-frag identity) ----
        uint32 p16[4][4];
        #pragma unroll
        for (int kk = 0; kk < 4; kk++) {
            p16[kk][0] = pack_h2(s[2*kk][0],   s[2*kk][1]);
            p16[kk][1] = pack_h2(s[2*kk][2],   s[2*kk][3]);
            p16[kk][2] = pack_h2(s[2*kk+1][0], s[2*kk+1][1]);
            p16[kk][3] = pack_h2(s[2*kk+1][2], s[2*kk+1][3]);
        }

        // ---- O += P V (single-term fp16) ----
        #pragma unroll
        for (int kk = 0; kk < 4; kk++) {
            uint32 v4[4][4];
            #pragma unroll
            for (int g = 0; g < 4; g++)
                ldsm_x4_t(v4[g], vb + (uint32)(kk * 2304 + g * 32) + vOffBase);
            #pragma unroll
            for (int g = 0; g < 4; g++) {
                mma_f16(o[2*g],   p16[kk], v4[g][0], v4[g][1]);
                mma_f16(o[2*g+1], p16[kk], v4[g][2], v4[g][3]);
            }
        }
        __syncthreads();
    }

    // ---- finalize: reduce l across quad, normalize, fp16 store ----
    l0 += __shfl_xor_sync(0xffffffffu, l0, 1);
    l0 += __shfl_xor_sync(0xffffffffu, l0, 2);
    l1 += __shfl_xor_sync(0xffffffffu, l1, 1);
    l1 += __shfl_xor_sync(0xffffffffu, l1, 2);
    float i0 = 1.f / l0, i1 = 1.f / l1;
    #pragma unroll
    for (int t = 0; t < 8; t++) {
        int col = h * HD + t * 8 + 2 * tig;
        size_t d0 = ((size_t)(b * SEQ + row0)) * DMODEL + col;
        size_t d1 = ((size_t)(b * SEQ + row0 + 8)) * DMODEL + col;
        *(__half2*)&O16[d0] = __floats2half2_rn(o[t][0] * i0, o[t][1] * i0);
        *(__half2*)&O16[d1] = __floats2half2_rn(o[t][2] * i1, o[t][3] * i1);
    }
}

// ---------------------------------------------------------------------------
// Launch
// ---------------------------------------------------------------------------
extern "C" void kernel_launch(void* const* d_in, const int* in_sizes, int n_in,
                              void* d_out, int out_size)
{
    const float* hidden = (const float*)d_in[0];   // [B,S,D]
    const float* W_attn = (const float*)d_in[1];   // [D,3D]
    const float* b_attn = (const float*)d_in[2];   // [3D]
    const float* W_proj = (const float*)d_in[3];   // [D,D]
    const float* b_proj = (const float*)d_in[4];   // [D]
    float* out = (float*)d_out;                    // [B,S,D]

    __half *h16, *wa16, *wp16, *at16, *v16;
    __nv_bfloat16 *q_h, *q_l, *k_h, *k_l;
    cudaGetSymbolAddress((void**)&h16,  g_h16);
    cudaGetSymbolAddress((void**)&wa16, g_wa16);
    cudaGetSymbolAddress((void**)&wp16, g_wp16);
    cudaGetSymbolAddress((void**)&at16, g_at16);
    cudaGetSymbolAddress((void**)&v16,  g_v16);
    cudaGetSymbolAddress((void**)&q_h, g_q_h);
    cudaGetSymbolAddress((void**)&q_l, g_q_l);
    cudaGetSymbolAddress((void**)&k_h, g_k_h);
    cudaGetSymbolAddress((void**)&k_l, g_k_l);

    cudaFuncSetAttribute(gemm_fp16_kernel<0>,
                         cudaFuncAttributeMaxDynamicSharedMemorySize,
                         GEMM_SMEM_BYTES);
    cudaFuncSetAttribute(gemm_fp16_kernel<1>,
                         cudaFuncAttributeMaxDynamicSharedMemorySize,
                         GEMM_SMEM_BYTES);
    cudaFuncSetAttribute(attn_mma_kernel,
                         cudaFuncAttributeMaxDynamicSharedMemorySize,
                         ATTN_SMEM_BYTES);

    const int M = BATCH * SEQ;   // 4096

    // 0) fp32 -> fp16 converts
    {
        int n1 = M * DMODEL;
        conv_kernel<<<n1 / 1024, 256>>>(hidden, h16, n1);
        int n2 = DMODEL * 3 * DMODEL;
        conv_kernel<<<n2 / 1024, 256>>>(W_attn, wa16, n2);
        int n3 = DMODEL * DMODEL;
        conv_kernel<<<n3 / 1024, 256>>>(W_proj, wp16, n3);
    }
    // 1) QKV projection (fp16 mma) -> q/k bf16 hi/lo + v fp16, head-major
    {
        dim3 grid(3 * DMODEL / 128, M / 128);    // (24, 32)
        gemm_fp16_kernel<1><<<grid, 256, GEMM_SMEM_BYTES>>>(
            h16, wa16, b_attn, nullptr,
            q_h, q_l, k_h, k_l, v16, M, 3 * DMODEL, DMODEL);
    }
    // 2) causal attention -> fp16 output
    {
        dim3 grid(SEQ / 128, NHEAD, BATCH);      // (16, 16, 2)
        attn_mma_kernel<<<grid, 256, ATTN_SMEM_BYTES>>>(
            q_h, q_l, k_h, k_l, v16, at16);
    }
    // 3) output projection (fp16 mma) -> fp32 out
    {
        dim3 grid(DMODEL / 128, M / 128);        // (8, 32)
        gemm_fp16_kernel<0><<<grid, 256, GEMM_SMEM_BYTES>>>(
            at16, wp16, b_proj, out,
            nullptr, nullptr, nullptr, nullptr, nullptr,
            M, DMODEL, DMODEL);
    }
}

// round 14
// speedup vs baseline: 2.3320x; 1.1873x over previous
#include <cuda_runtime.h>
#include <cuda_bf16.h>
#include <cuda_fp16.h>
#include <math.h>

// Problem constants (fixed by the reference)
#define BATCH 2
#define SEQ   2048
#define DMODEL 1024
#define NHEAD 16
#define HD    64          // head dim
#define QKV_ROW (3*DMODEL)

typedef unsigned int uint32;

// ---- mma / ldmatrix / cp.async wrappers -----------------------------------
__device__ __forceinline__ void ldsm_x4(uint32 r[4], uint32 addr) {
    asm volatile("ldmatrix.sync.aligned.m8n8.x4.shared.b16 {%0,%1,%2,%3}, [%4];"
                 : "=r"(r[0]), "=r"(r[1]), "=r"(r[2]), "=r"(r[3]) : "r"(addr));
}
__device__ __forceinline__ void ldsm_x4_t(uint32 r[4], uint32 addr) {
    asm volatile("ldmatrix.sync.aligned.m8n8.x4.trans.shared.b16 {%0,%1,%2,%3}, [%4];"
                 : "=r"(r[0]), "=r"(r[1]), "=r"(r[2]), "=r"(r[3]) : "r"(addr));
}
__device__ __forceinline__ void mma_f16(float d[4], const uint32 a[4],
                                        uint32 b0, uint32 b1) {
    asm volatile(
        "mma.sync.aligned.m16n8k16.row.col.f32.f16.f16.f32 "
        "{%0,%1,%2,%3}, {%4,%5,%6,%7}, {%8,%9}, {%10,%11,%12,%13};"
        : "=f"(d[0]), "=f"(d[1]), "=f"(d[2]), "=f"(d[3])
        : "r"(a[0]), "r"(a[1]), "r"(a[2]), "r"(a[3]),
          "r"(b0), "r"(b1),
          "f"(d[0]), "f"(d[1]), "f"(d[2]), "f"(d[3]));
}
__device__ __forceinline__ void cp16(uint32 smem_addr, const void* gptr) {
    asm volatile("cp.async.ca.shared.global [%0], [%1], 16;\n"
                 :: "r"(smem_addr), "l"(gptr));
}
__device__ __forceinline__ void cp_commit() {
    asm volatile("cp.async.commit_group;\n");
}
template<int N> __device__ __forceinline__ void cp_wait() {
    asm volatile("cp.async.wait_group %0;\n" :: "n"(N));
}
__device__ __forceinline__ uint32 pack_h2(float x, float y) {
    __half2 h = __floats2half2_rn(x, y);
    return *reinterpret_cast<uint32*>(&h);
}

// Scratch (allocation-free rule: __device__ globals)
__device__ __half g_h16[(size_t)BATCH*SEQ*DMODEL];        // fp16 hidden
__device__ __half g_wa16[(size_t)DMODEL*3*DMODEL];        // fp16 W_attn
__device__ __half g_wp16[(size_t)DMODEL*DMODEL];          // fp16 W_proj
__device__ __half g_at16[(size_t)BATCH*SEQ*DMODEL];       // fp16 attn out
// head-major [B][H][S][HD] fp16: q (pre-scaled 1/8), k, v
#define HEADS_ELEMS ((size_t)BATCH*NHEAD*SEQ*HD)
__device__ __half g_q16[HEADS_ELEMS];
__device__ __half g_k16[HEADS_ELEMS];
__device__ __half g_v16[HEADS_ELEMS];

// ---------------------------------------------------------------------------
// fp32 -> fp16 convert
// ---------------------------------------------------------------------------
__global__ __launch_bounds__(256)
void conv_kernel(const float* __restrict__ x, __half* __restrict__ y, int n)
{
    int i = (blockIdx.x * 256 + threadIdx.x) * 4;
    if (i >= n) return;
    float4 v = *(const float4*)&x[i];
    *(__half2*)&y[i]     = __floats2half2_rn(v.x, v.y);
    *(__half2*)&y[i + 2] = __floats2half2_rn(v.z, v.w);
}

// ---------------------------------------------------------------------------
// Tensor-core fp16 GEMM (fp32 accumulate), cp.async double buffered.
// C[M,N] = A[M,K] @ W[K,N] + bias.
// BM=128, BN=128, BK=32, 256 threads / 8 warps (4m x 2n), warp tile 32x64.
// MODE 0: bias + fp32 store.  MODE 1: bias, q-scale, fp16 head-major scatter
// to Q/K/V (N = 3*DMODEL).
// ---------------------------------------------------------------------------
#define GEMM_SMEM_BYTES 37888
template<int MODE>
__global__ __launch_bounds__(256, 2)
void gemm_fp16_kernel(const __half* __restrict__ A,
                      const __half* __restrict__ W,
                      const float* __restrict__ bias,
                      float* __restrict__ C,
                      __half* __restrict__ Q16,
                      __half* __restrict__ K16,
                      __half* __restrict__ V16,
                      int M, int N, int K)
{
    extern __shared__ uint4 dsm[];
    uint32 base = (uint32)__cvta_generic_to_shared(dsm);
    const uint32 oA = 0, oW = 20480;
    const uint32 stA = 10240, stW = 8704;

    const int tid  = threadIdx.x;
    const int lane = tid & 31;
    const int wid  = tid >> 5;
    const int warp_m = wid & 3;
    const int warp_n = wid >> 2;
    const int row0 = blockIdx.y * 128;
    const int col0 = blockIdx.x * 128;

    // ldmatrix lane offsets
    const int j  = lane & 7;
    const int q  = lane >> 3;
    const int a_row_off = j + (q & 1) * 8;
    const int a_chk_off = q >> 1;
    uint32 aOff[2];
    #pragma unroll
    for (int ma = 0; ma < 2; ma++) {
        int r = warp_m * 32 + ma * 16 + a_row_off;
        aOff[ma] = (uint32)(r * 5 + a_chk_off) * 16;
    }
    uint32 wOff[4];
    #pragma unroll
    for (int nb = 0; nb < 4; nb++) {
        int k = j + (q & 1) * 8;
        int chk = (warp_n * 64 + nb * 16) / 8 + (q >> 1);
        wOff[nb] = (uint32)(k * 17 + chk) * 16;
    }

    // loader coordinates: 2 chunks per array per thread
    int aR[2], aC[2], wR[2], wC[2];
    #pragma unroll
    for (int t = 0; t < 2; t++) {
        int id = tid + t * 256;
        aR[t] = id >> 2;  aC[t] = id & 3;
        wR[t] = id >> 4;  wC[t] = id & 15;
    }

    float acc[2][8][4];
    #pragma unroll
    for (int ma = 0; ma < 2; ma++)
        #pragma unroll
        for (int na = 0; na < 8; na++)
            #pragma unroll
            for (int i = 0; i < 4; i++)
                acc[ma][na][i] = 0.f;

    const int nkt = K / 32;
    // prologue: stage 0
    #pragma unroll
    for (int t = 0; t < 2; t++) {
        cp16(base + oA + (uint32)(aR[t] * 5 + aC[t]) * 16,
             &A[(size_t)(row0 + aR[t]) * K + aC[t] * 8]);
        cp16(base + oW + (uint32)(wR[t] * 17 + wC[t]) * 16,
             &W[(size_t)(wR[t]) * N + col0 + wC[t] * 8]);
    }
    cp_commit();

    for (int kt = 0; kt < nkt; kt++) {
        if (kt + 1 < nkt) {
            uint32 st = (uint32)((kt + 1) & 1);
            int k0n = (kt + 1) * 32;
            #pragma unroll
            for (int t = 0; t < 2; t++) {
                cp16(base + oA + st * stA + (uint32)(aR[t] * 5 + aC[t]) * 16,
                     &A[(size_t)(row0 + aR[t]) * K + k0n + aC[t] * 8]);
                cp16(base + oW + st * stW + (uint32)(wR[t] * 17 + wC[t]) * 16,
                     &W[(size_t)(k0n + wR[t]) * N + col0 + wC[t] * 8]);
            }
            cp_commit();
            cp_wait<1>();
        } else {
            cp_wait<0>();
        }
        __syncthreads();

        uint32 st = (uint32)(kt & 1);
        uint32 bA = base + oA + st * stA;
        uint32 bW = base + oW + st * stW;

        #pragma unroll
        for (int ks = 0; ks < 2; ks++) {
            uint32 af[2][4], bf[4][4];
            ldsm_x4(af[0], bA + aOff[0] + ks * 32);
            ldsm_x4(af[1], bA + aOff[1] + ks * 32);
            #pragma unroll
            for (int nb = 0; nb < 4; nb++)
                ldsm_x4_t(bf[nb], bW + wOff[nb] + ks * 4352);  // +16 k * 272B
            #pragma unroll
            for (int nb = 0; nb < 4; nb++)
                #pragma unroll
                for (int ma = 0; ma < 2; ma++) {
                    mma_f16(acc[ma][2*nb],   af[ma], bf[nb][0], bf[nb][1]);
                    mma_f16(acc[ma][2*nb+1], af[ma], bf[nb][2], bf[nb][3]);
                }
        }
        __syncthreads();
    }

    // ---- epilogue ----
    int r_base = row0 + warp_m * 32 + (lane >> 2);
    int c_base = col0 + warp_n * 64 + (lane & 3) * 2;
    #pragma unroll
    for (int ma = 0; ma < 2; ma++) {
        #pragma unroll
        for (int na = 0; na < 8; na++) {
            int c = c_base + na * 8;
            float bx = bias[c], by = bias[c + 1];
            #pragma unroll
            for (int half_i = 0; half_i < 2; half_i++) {
                int r = r_base + ma * 16 + half_i * 8;
                float vx = acc[ma][na][2 * half_i + 0] + bx;
                float vy = acc[ma][na][2 * half_i + 1] + by;
                if (MODE == 0) {
                    *(float2*)&C[(size_t)r * N + c] = make_float2(vx, vy);
                } else {
                    int arr = c >> 10;               // 0=q 1=k 2=v
                    int hh  = (c >> 6) & 15;
                    int dd  = c & 63;
                    int bb  = r >> 11, ss = r & 2047;
                    size_t dst = (((size_t)(bb * NHEAD + hh)) * SEQ + ss) * HD + dd;
                    if (arr == 0) { vx *= 0.125f; vy *= 0.125f; }
                    __half* p = (arr == 0) ? Q16 : (arr == 1) ? K16 : V16;
                    *(__half2*)&p[dst] = __floats2half2_rn(vx, vy);
                }
            }
        }
    }
}

// ---------------------------------------------------------------------------
// Fully-fp16 MMA causal flash attention (fp32 softmax/accumulators).
// QK single-term fp16, PV single-term fp16.
// BM=128 q rows/block, BN=64 keys/tile, 8 warps (warp = 16 q rows).
// smem per stage: K16[64][72], V16[64][72] fp16 (9216 B each, rows 144 B
// padded); stage stride 18432 B, double buffered.
// ---------------------------------------------------------------------------
#define ATTN_SMEM_BYTES (2 * 18432)
__global__ __launch_bounds__(256, 2)
void attn_mma_kernel(const __half* __restrict__ Q16,
                     const __half* __restrict__ K16,
                     const __half* __restrict__ V16,
                     __half* __restrict__ O16)
{
    extern __shared__ uint4 dsm[];
    uint32 smem_u = (uint32)__cvta_generic_to_shared(dsm);

    const int tid  = threadIdx.x;
    const int lane = tid & 31;
    const int wq   = tid >> 5;
    const int qt = (int)gridDim.x - 1 - (int)blockIdx.x;
    const int h = blockIdx.y, b = blockIdx.z;
    const int q0 = qt * 128;
    const size_t headoff = ((size_t)(b * NHEAD + h)) * SEQ * HD;

    const int gid = lane >> 2;
    const int tig = lane & 3;
    const int row0 = q0 + wq * 16 + gid;

    // ---- Q fragments straight from global (fp16 pairs) ----
    uint32 qf[4][4];
    {
        const __half* Qb = Q16 + headoff;
        #pragma unroll
        for (int ks = 0; ks < 4; ks++) {
            int kc = ks * 16 + 2 * tig;
            qf[ks][0] = *(const uint32*)&Qb[(size_t)row0 * HD + kc];
            qf[ks][1] = *(const uint32*)&Qb[(size_t)(row0 + 8) * HD + kc];
            qf[ks][2] = *(const uint32*)&Qb[(size_t)row0 * HD + kc + 8];
            qf[ks][3] = *(const uint32*)&Qb[(size_t)(row0 + 8) * HD + kc + 8];
        }
    }

    const uint32 kOffBase = (uint32)((((lane >> 4) << 3) + (lane & 7)) * 144
                                     + ((lane >> 3) & 1) * 16);
    const uint32 vOffBase = (uint32)(((lane & 7) + (((lane >> 3) & 1) << 3)) * 144
                                     + (lane >> 4) * 16);

    float o[8][4];
    #pragma unroll
    for (int t = 0; t < 8; t++)
        #pragma unroll
        for (int i = 0; i < 4; i++) o[t][i] = 0.f;
    float m0 = -INFINITY, m1 = -INFINITY, l0 = 0.f, l1 = 0.f;

    const __half* kvsrc[2] = {K16 + headoff, V16 + headoff};
    const int ntiles = 2 * (qt + 1);

    // tile loader: 2 arrays x 64 rows x 8 chunks = 1024 chunks, 4/thread
    {
        #pragma unroll
        for (int t = 0; t < 4; t++) {
            int id = tid + t * 256;
            int arr = id >> 9;
            int r = (id >> 3) & 63;
            int c = id & 7;
            cp16(smem_u + (uint32)(arr * 9216 + r * 144 + c * 16),
                 kvsrc[arr] + (size_t)r * HD + c * 8);
        }
        cp_commit();
    }

    for (int tt = 0; tt < ntiles; tt++) {
        int kb = tt * 64;
        if (tt + 1 < ntiles) {
            uint32 stn = (uint32)((tt + 1) & 1) * 18432;
            int kbn = kb + 64;
            #pragma unroll
            for (int t = 0; t < 4; t++) {
                int id = tid + t * 256;
                int arr = id >> 9;
                int r = (id >> 3) & 63;
                int c = id & 7;
                cp16(smem_u + stn + (uint32)(arr * 9216 + r * 144 + c * 16),
                     kvsrc[arr] + (size_t)(kbn + r) * HD + c * 8);
            }
            cp_commit();
            cp_wait<1>();
        } else {
            cp_wait<0>();
        }
        __syncthreads();

        uint32 stb = smem_u + (uint32)(tt & 1) * 18432;
        uint32 kbse = stb, vbse = stb + 9216;

        // ---- S = Q K^T (single-term fp16) ----
        float s[8][4];
        #pragma unroll
        for (int t = 0; t < 8; t++)
            #pragma unroll
            for (int i = 0; i < 4; i++) s[t][i] = 0.f;

        #pragma unroll
        for (int ks = 0; ks < 4; ks++) {
            uint32 kf[4][4];
            #pragma unroll
            for (int g = 0; g < 4; g++)
                ldsm_x4(kf[g], kbse + (uint32)(g * 2304 + ks * 32) + kOffBase);
            #pragma unroll
            for (int g = 0; g < 4; g++) {
                mma_f16(s[2*g],   qf[ks], kf[g][0], kf[g][1]);
                mma_f16(s[2*g+1], qf[ks], kf[g][2], kf[g][3]);
            }
        }

        // ---- causal mask (diagonal tiles only) ----
        if (kb + 63 > q0 + wq * 16) {
            #pragma unroll
            for (int t = 0; t < 8; t++) {
                int key = kb + t * 8 + 2 * tig;
                if (key     > row0)     s[t][0] = -INFINITY;
                if (key + 1 > row0)     s[t][1] = -INFINITY;
                if (key     > row0 + 8) s[t][2] = -INFINITY;
                if (key + 1 > row0 + 8) s[t][3] = -INFINITY;
            }
        }

        // ---- online softmax ----
        float r0 = -INFINITY, r1 = -INFINITY;
        #pragma unroll
        for (int t = 0; t < 8; t++) {
            r0 = fmaxf(r0, fmaxf(s[t][0], s[t][1]));
            r1 = fmaxf(r1, fmaxf(s[t][2], s[t][3]));
        }
        r0 = fmaxf(r0, __shfl_xor_sync(0xffffffffu, r0, 1));
        r0 = fmaxf(r0, __shfl_xor_sync(0xffffffffu, r0, 2));
        r1 = fmaxf(r1, __shfl_xor_sync(0xffffffffu, r1, 1));
        r1 = fmaxf(r1, __shfl_xor_sync(0xffffffffu, r1, 2));
        float mn0 = fmaxf(m0, r0), mn1 = fmaxf(m1, r1);
        float c0 = __expf(m0 - mn0), c1 = __expf(m1 - mn1);
        m0 = mn0; m1 = mn1;
        l0 *= c0;  l1 *= c1;
        #pragma unroll
        for (int t = 0; t < 8; t++) {
            s[t][0] = __expf(s[t][0] - m0);
            s[t][1] = __expf(s[t][1] - m0);
            s[t][2] = __expf(s[t][2] - m1);
            s[t][3] = __expf(s[t][3] - m1);
            l0 += s[t][0] + s[t][1];
            l1 += s[t][2] + s[t][3];
        }
        #pragma unroll
        for (int t = 0; t < 8; t++) {
            o[t][0] *= c0; o[t][1] *= c0;
            o[t][2] *= c1; o[t][3] *= c1;
        }

        // ---- pack P fp16 (C-frag == A-frag identity) ----
        uint32 p16[4][4];
        #pragma unroll
        for (int kk = 0; kk < 4; kk++) {
            p16[kk][0] = pack_h2(s[2*kk][0],   s[2*kk][1]);
            p16[kk][1] = pack_h2(s[2*kk][2],   s[2*kk][3]);
            p16[kk][2] = pack_h2(s[2*kk+1][0], s[2*kk+1][1]);
            p16[kk][3] = pack_h2(s[2*kk+1][2], s[2*kk+1][3]);
        }

        // ---- O += P V (single-term fp16) ----
        #pragma unroll
        for (int kk = 0; kk < 4; kk++) {
            uint32 v4[4][4];
            #pragma unroll
            for (int g = 0; g < 4; g++)
                ldsm_x4_t(v4[g], vbse + (uint32)(kk * 2304 + g * 32) + vOffBase);
            #pragma unroll
            for (int g = 0; g < 4; g++) {
                mma_f16(o[2*g],   p16[kk], v4[g][0], v4[g][1]);
                mma_f16(o[2*g+1], p16[kk], v4[g][2], v4[g][3]);
            }
        }
        __syncthreads();
    }

    // ---- finalize: reduce l across quad, normalize, fp16 store ----
    l0 += __shfl_xor_sync(0xffffffffu, l0, 1);
    l0 += __shfl_xor_sync(0xffffffffu, l0, 2);
    l1 += __shfl_xor_sync(0xffffffffu, l1, 1);
    l1 += __shfl_xor_sync(0xffffffffu, l1, 2);
    float i0 = 1.f / l0, i1 = 1.f / l1;
    #pragma unroll
    for (int t = 0; t < 8; t++) {
        int col = h * HD + t * 8 + 2 * tig;
        size_t d0 = ((size_t)(b * SEQ + row0)) * DMODEL + col;
        size_t d1 = ((size_t)(b * SEQ + row0 + 8)) * DMODEL + col;
        *(__half2*)&O16[d0] = __floats2half2_rn(o[t][0] * i0, o[t][1] * i0);
        *(__half2*)&O16[d1] = __floats2half2_rn(o[t][2] * i1, o[t][3] * i1);
    }
}

// ---------------------------------------------------------------------------
// Launch
// ---------------------------------------------------------------------------
extern "C" void kernel_launch(void* const* d_in, const int* in_sizes, int n_in,
                              void* d_out, int out_size)
{
    const float* hidden = (const float*)d_in[0];   // [B,S,D]
    const float* W_attn = (const float*)d_in[1];   // [D,3D]
    const float* b_attn = (const float*)d_in[2];   // [3D]
    const float* W_proj = (const float*)d_in[3];   // [D,D]
    const float* b_proj = (const float*)d_in[4];   // [D]
    float* out = (float*)d_out;                    // [B,S,D]

    __half *h16, *wa16, *wp16, *at16, *q16, *k16, *v16;
    cudaGetSymbolAddress((void**)&h16,  g_h16);
    cudaGetSymbolAddress((void**)&wa16, g_wa16);
    cudaGetSymbolAddress((void**)&wp16, g_wp16);
    cudaGetSymbolAddress((void**)&at16, g_at16);
    cudaGetSymbolAddress((void**)&q16,  g_q16);
    cudaGetSymbolAddress((void**)&k16,  g_k16);
    cudaGetSymbolAddress((void**)&v16,  g_v16);

    cudaFuncSetAttribute(gemm_fp16_kernel<0>,
                         cudaFuncAttributeMaxDynamicSharedMemorySize,
                         GEMM_SMEM_BYTES);
    cudaFuncSetAttribute(gemm_fp16_kernel<1>,
                         cudaFuncAttributeMaxDynamicSharedMemorySize,
                         GEMM_SMEM_BYTES);
    cudaFuncSetAttribute(attn_mma_kernel,
                         cudaFuncAttributeMaxDynamicSharedMemorySize,
                         ATTN_SMEM_BYTES);

    const int M = BATCH * SEQ;   // 4096

    // 0) fp32 -> fp16 converts
    {
        int n1 = M * DMODEL;
        conv_kernel<<<n1 / 1024, 256>>>(hidden, h16, n1);
        int n2 = DMODEL * 3 * DMODEL;
        conv_kernel<<<n2 / 1024, 256>>>(W_attn, wa16, n2);
        int n3 = DMODEL * DMODEL;
        conv_kernel<<<n3 / 1024, 256>>>(W_proj, wp16, n3);
    }
    // 1) QKV projection (fp16 mma) -> fp16 head-major q(scaled)/k/v
    {
        dim3 grid(3 * DMODEL / 128, M / 128);    // (24, 32)
        gemm_fp16_kernel<1><<<grid, 256, GEMM_SMEM_BYTES>>>(
            h16, wa16, b_attn, nullptr, q16, k16, v16, M, 3 * DMODEL, DMODEL);
    }
    // 2) causal attention (fully fp16 mma) -> fp16 output
    {
        dim3 grid(SEQ / 128, NHEAD, BATCH);      // (16, 16, 2)
        attn_mma_kernel<<<grid, 256, ATTN_SMEM_BYTES>>>(q16, k16, v16, at16);
    }
    // 3) output projection (fp16 mma) -> fp32 out
    {
        dim3 grid(DMODEL / 128, M / 128);        // (8, 32)
        gemm_fp16_kernel<0><<<grid, 256, GEMM_SMEM_BYTES>>>(
            at16, wp16, b_proj, out, nullptr, nullptr, nullptr,
            M, DMODEL, DMODEL);
    }
}

// round 15
// speedup vs baseline: 2.5407x; 1.0895x over previous
#include <cuda_runtime.h>
#include <cuda_bf16.h>
#include <cuda_fp16.h>
#include <math.h>

// Problem constants (fixed by the reference)
#define BATCH 2
#define SEQ   2048
#define DMODEL 1024
#define NHEAD 16
#define HD    64          // head dim
#define QKV_ROW (3*DMODEL)

typedef unsigned int uint32;

// ---- mma / ldmatrix / cp.async wrappers -----------------------------------
__device__ __forceinline__ void ldsm_x4(uint32 r[4], uint32 addr) {
    asm volatile("ldmatrix.sync.aligned.m8n8.x4.shared.b16 {%0,%1,%2,%3}, [%4];"
                 : "=r"(r[0]), "=r"(r[1]), "=r"(r[2]), "=r"(r[3]) : "r"(addr));
}
__device__ __forceinline__ void ldsm_x4_t(uint32 r[4], uint32 addr) {
    asm volatile("ldmatrix.sync.aligned.m8n8.x4.trans.shared.b16 {%0,%1,%2,%3}, [%4];"
                 : "=r"(r[0]), "=r"(r[1]), "=r"(r[2]), "=r"(r[3]) : "r"(addr));
}
__device__ __forceinline__ void mma_f16(float d[4], const uint32 a[4],
                                        uint32 b0, uint32 b1) {
    asm volatile(
        "mma.sync.aligned.m16n8k16.row.col.f32.f16.f16.f32 "
        "{%0,%1,%2,%3}, {%4,%5,%6,%7}, {%8,%9}, {%10,%11,%12,%13};"
        : "=f"(d[0]), "=f"(d[1]), "=f"(d[2]), "=f"(d[3])
        : "r"(a[0]), "r"(a[1]), "r"(a[2]), "r"(a[3]),
          "r"(b0), "r"(b1),
          "f"(d[0]), "f"(d[1]), "f"(d[2]), "f"(d[3]));
}
__device__ __forceinline__ void cp16(uint32 smem_addr, const void* gptr) {
    asm volatile("cp.async.ca.shared.global [%0], [%1], 16;\n"
                 :: "r"(smem_addr), "l"(gptr));
}
__device__ __forceinline__ void cp_commit() {
    asm volatile("cp.async.commit_group;\n");
}
template<int N> __device__ __forceinline__ void cp_wait() {
    asm volatile("cp.async.wait_group %0;\n" :: "n"(N));
}
__device__ __forceinline__ uint32 pack_h2(float x, float y) {
    __half2 h = __floats2half2_rn(x, y);
    return *reinterpret_cast<uint32*>(&h);
}

// Scratch (allocation-free rule: __device__ globals)
__device__ __half g_h16[(size_t)BATCH*SEQ*DMODEL];        // fp16 hidden
__device__ __half g_wa16[(size_t)DMODEL*3*DMODEL];        // fp16 W_attn
__device__ __half g_wp16[(size_t)DMODEL*DMODEL];          // fp16 W_proj
__device__ __half g_at16[(size_t)BATCH*SEQ*DMODEL];       // fp16 attn out
// head-major [B][H][S][HD] fp16: q (pre-scaled 1/8), k, v
#define HEADS_ELEMS ((size_t)BATCH*NHEAD*SEQ*HD)
__device__ __half g_q16[HEADS_ELEMS];
__device__ __half g_k16[HEADS_ELEMS];
__device__ __half g_v16[HEADS_ELEMS];

// ---------------------------------------------------------------------------
// Fused fp32 -> fp16 convert over three arrays (one launch).
// ---------------------------------------------------------------------------
__global__ __launch_bounds__(256)
void conv3_kernel(const float* __restrict__ x0, __half* __restrict__ y0, int n0,
                  const float* __restrict__ x1, __half* __restrict__ y1, int n1,
                  const float* __restrict__ x2, __half* __restrict__ y2, int n2)
{
    int i = (blockIdx.x * 256 + threadIdx.x) * 4;
    const float* x; __half* y;
    if (i < n0)            { x = x0; y = y0; }
    else if (i < n0 + n1)  { i -= n0; x = x1; y = y1; }
    else                   { i -= n0 + n1; if (i >= n2) return; x = x2; y = y2; }
    float4 v = *(const float4*)&x[i];
    *(__half2*)&y[i]     = __floats2half2_rn(v.x, v.y);
    *(__half2*)&y[i + 2] = __floats2half2_rn(v.z, v.w);
}

// ---------------------------------------------------------------------------
// Tensor-core fp16 GEMM (fp32 accumulate), cp.async double buffered,
// BK=64, ONE barrier per k-tile (wait -> barrier -> issue-next -> compute).
// C[M,N] = A[M,K] @ W[K,N] + bias.
// BM=128, BN=128, 256 threads / 8 warps (4m x 2n), warp tile 32x64.
// MODE 0: bias + fp32 store.  MODE 1: bias, q-scale, fp16 head-major scatter
// to Q/K/V (N = 3*DMODEL).
// smem: A stage 128 rows x 9 chunks (18432 B) x2 @0,
//       W stage  64 rows x 17 chunks (17408 B) x2 @36864.  Total 71680 B.
// ---------------------------------------------------------------------------
#define GEMM_SMEM_BYTES 71680
template<int MODE>
__global__ __launch_bounds__(256, 2)
void gemm_fp16_kernel(const __half* __restrict__ A,
                      const __half* __restrict__ W,
                      const float* __restrict__ bias,
                      float* __restrict__ C,
                      __half* __restrict__ Q16,
                      __half* __restrict__ K16,
                      __half* __restrict__ V16,
                      int M, int N, int K)
{
    extern __shared__ uint4 dsm[];
    uint32 base = (uint32)__cvta_generic_to_shared(dsm);
    const uint32 oW = 36864;
    const uint32 stA = 18432, stW = 17408;

    const int tid  = threadIdx.x;
    const int lane = tid & 31;
    const int wid  = tid >> 5;
    const int warp_m = wid & 3;
    const int warp_n = wid >> 2;
    const int row0 = blockIdx.y * 128;
    const int col0 = blockIdx.x * 128;

    // ldmatrix lane offsets
    const int j  = lane & 7;
    const int q  = lane >> 3;
    const int a_row_off = j + (q & 1) * 8;
    const int a_chk_off = q >> 1;           // 16B chunk within row (ks=0)
    uint32 aOff[2];
    #pragma unroll
    for (int ma = 0; ma < 2; ma++) {
        int r = warp_m * 32 + ma * 16 + a_row_off;
        aOff[ma] = (uint32)(r * 9 + a_chk_off) * 16;
    }
    uint32 wOff[4];
    #pragma unroll
    for (int nb = 0; nb < 4; nb++) {
        int k = j + (q & 1) * 8;
        int chk = warp_n * 8 + nb * 2 + (q >> 1);
        wOff[nb] = (uint32)(k * 17 + chk) * 16;
    }

    // loader coordinates: 4 chunks per array per thread
    int aR[4], aC[4], wR[4], wC[4];
    #pragma unroll
    for (int t = 0; t < 4; t++) {
        int id = tid + t * 256;
        aR[t] = id >> 3;  aC[t] = id & 7;    // 128 x 8
        wR[t] = id >> 4;  wC[t] = id & 15;   // 64 x 16
    }

    float acc[2][8][4];
    #pragma unroll
    for (int ma = 0; ma < 2; ma++)
        #pragma unroll
        for (int na = 0; na < 8; na++)
            #pragma unroll
            for (int i = 0; i < 4; i++)
                acc[ma][na][i] = 0.f;

    auto load_stage = [&](int s) {
        uint32 bA = base + (uint32)(s & 1) * stA;
        uint32 bW = base + oW + (uint32)(s & 1) * stW;
        int k0 = s * 64;
        #pragma unroll
        for (int t = 0; t < 4; t++) {
            cp16(bA + (uint32)(aR[t] * 9 + aC[t]) * 16,
                 &A[(size_t)(row0 + aR[t]) * K + k0 + aC[t] * 8]);
            cp16(bW + (uint32)(wR[t] * 17 + wC[t]) * 16,
                 &W[(size_t)(k0 + wR[t]) * N + col0 + wC[t] * 8]);
        }
        cp_commit();
    };

    const int nkt = K / 64;   // 16
    load_stage(0);

    for (int kt = 0; kt < nkt; kt++) {
        cp_wait<0>();          // stage kt resident
        __syncthreads();       // data visible AND previous buffer drained
        if (kt + 1 < nkt) load_stage(kt + 1);   // fills the drained buffer

        uint32 bA = base + (uint32)(kt & 1) * stA;
        uint32 bW = base + oW + (uint32)(kt & 1) * stW;

        #pragma unroll
        for (int ks = 0; ks < 4; ks++) {
            uint32 af[2][4], bf[4][4];
            ldsm_x4(af[0], bA + aOff[0] + ks * 32);
            ldsm_x4(af[1], bA + aOff[1] + ks * 32);
            #pragma unroll
            for (int nb = 0; nb < 4; nb++)
                ldsm_x4_t(bf[nb], bW + wOff[nb] + ks * 4352);  // +16 k-rows*272B
            #pragma unroll
            for (int nb = 0; nb < 4; nb++)
                #pragma unroll
                for (int ma = 0; ma < 2; ma++) {
                    mma_f16(acc[ma][2*nb],   af[ma], bf[nb][0], bf[nb][1]);
                    mma_f16(acc[ma][2*nb+1], af[ma], bf[nb][2], bf[nb][3]);
                }
        }
    }

    // ---- epilogue ----
    int r_base = row0 + warp_m * 32 + (lane >> 2);
    int c_base = col0 + warp_n * 64 + (lane & 3) * 2;
    #pragma unroll
    for (int ma = 0; ma < 2; ma++) {
        #pragma unroll
        for (int na = 0; na < 8; na++) {
            int c = c_base + na * 8;
            float bx = bias[c], by = bias[c + 1];
            #pragma unroll
            for (int half_i = 0; half_i < 2; half_i++) {
                int r = r_base + ma * 16 + half_i * 8;
                float vx = acc[ma][na][2 * half_i + 0] + bx;
                float vy = acc[ma][na][2 * half_i + 1] + by;
                if (MODE == 0) {
                    *(float2*)&C[(size_t)r * N + c] = make_float2(vx, vy);
                } else {
                    int arr = c >> 10;               // 0=q 1=k 2=v
                    int hh  = (c >> 6) & 15;
                    int dd  = c & 63;
                    int bb  = r >> 11, ss = r & 2047;
                    size_t dst = (((size_t)(bb * NHEAD + hh)) * SEQ + ss) * HD + dd;
                    if (arr == 0) { vx *= 0.125f; vy *= 0.125f; }
                    __half* p = (arr == 0) ? Q16 : (arr == 1) ? K16 : V16;
                    *(__half2*)&p[dst] = __floats2half2_rn(vx, vy);
                }
            }
        }
    }
}

// ---------------------------------------------------------------------------
// Fully-fp16 MMA causal flash attention (fp32 softmax/accumulators).
// QK single-term fp16, PV single-term fp16.  (unchanged from R14)
// BM=128 q rows/block, BN=64 keys/tile, 8 warps (warp = 16 q rows).
// ---------------------------------------------------------------------------
#define ATTN_SMEM_BYTES (2 * 18432)
__global__ __launch_bounds__(256, 2)
void attn_mma_kernel(const __half* __restrict__ Q16,
                     const __half* __restrict__ K16,
                     const __half* __restrict__ V16,
                     __half* __restrict__ O16)
{
    extern __shared__ uint4 dsm[];
    uint32 smem_u = (uint32)__cvta_generic_to_shared(dsm);

    const int tid  = threadIdx.x;
    const int lane = tid & 31;
    const int wq   = tid >> 5;
    const int qt = (int)gridDim.x - 1 - (int)blockIdx.x;
    const int h = blockIdx.y, b = blockIdx.z;
    const int q0 = qt * 128;
    const size_t headoff = ((size_t)(b * NHEAD + h)) * SEQ * HD;

    const int gid = lane >> 2;
    const int tig = lane & 3;
    const int row0 = q0 + wq * 16 + gid;

    // ---- Q fragments straight from global (fp16 pairs) ----
    uint32 qf[4][4];
    {
        const __half* Qb = Q16 + headoff;
        #pragma unroll
        for (int ks = 0; ks < 4; ks++) {
            int kc = ks * 16 + 2 * tig;
            qf[ks][0] = *(const uint32*)&Qb[(size_t)row0 * HD + kc];
            qf[ks][1] = *(const uint32*)&Qb[(size_t)(row0 + 8) * HD + kc];
            qf[ks][2] = *(const uint32*)&Qb[(size_t)row0 * HD + kc + 8];
            qf[ks][3] = *(const uint32*)&Qb[(size_t)(row0 + 8) * HD + kc + 8];
        }
    }

    const uint32 kOffBase = (uint32)((((lane >> 4) << 3) + (lane & 7)) * 144
                                     + ((lane >> 3) & 1) * 16);
    const uint32 vOffBase = (uint32)(((lane & 7) + (((lane >> 3) & 1) << 3)) * 144
                                     + (lane >> 4) * 16);

    float o[8][4];
    #pragma unroll
    for (int t = 0; t < 8; t++)
        #pragma unroll
        for (int i = 0; i < 4; i++) o[t][i] = 0.f;
    float m0 = -INFINITY, m1 = -INFINITY, l0 = 0.f, l1 = 0.f;

    const __half* kvsrc[2] = {K16 + headoff, V16 + headoff};
    const int ntiles = 2 * (qt + 1);

    // tile loader: 2 arrays x 64 rows x 8 chunks = 1024 chunks, 4/thread
    {
        #pragma unroll
        for (int t = 0; t < 4; t++) {
            int id = tid + t * 256;
            int arr = id >> 9;
            int r = (id >> 3) & 63;
            int c = id & 7;
            cp16(smem_u + (uint32)(arr * 9216 + r * 144 + c * 16),
                 kvsrc[arr] + (size_t)r * HD + c * 8);
        }
        cp_commit();
    }

    for (int tt = 0; tt < ntiles; tt++) {
        int kb = tt * 64;
        if (tt + 1 < ntiles) {
            uint32 stn = (uint32)((tt + 1) & 1) * 18432;
            int kbn = kb + 64;
            #pragma unroll
            for (int t = 0; t < 4; t++) {
                int id = tid + t * 256;
                int arr = id >> 9;
                int r = (id >> 3) & 63;
                int c = id & 7;
                cp16(smem_u + stn + (uint32)(arr * 9216 + r * 144 + c * 16),
                     kvsrc[arr] + (size_t)(kbn + r) * HD + c * 8);
            }
            cp_commit();
            cp_wait<1>();
        } else {
            cp_wait<0>();
        }
        __syncthreads();

        uint32 stb = smem_u + (uint32)(tt & 1) * 18432;
        uint32 kbse = stb, vbse = stb + 9216;

        // ---- S = Q K^T (single-term fp16) ----
        float s[8][4];
        #pragma unroll
        for (int t = 0; t < 8; t++)
            #pragma unroll
            for (int i = 0; i < 4; i++) s[t][i] = 0.f;

        #pragma unroll
        for (int ks = 0; ks < 4; ks++) {
            uint32 kf[4][4];
            #pragma unroll
            for (int g = 0; g < 4; g++)
                ldsm_x4(kf[g], kbse + (uint32)(g * 2304 + ks * 32) + kOffBase);
            #pragma unroll
            for (int g = 0; g < 4; g++) {
                mma_f16(s[2*g],   qf[ks], kf[g][0], kf[g][1]);
                mma_f16(s[2*g+1], qf[ks], kf[g][2], kf[g][3]);
            }
        }

        // ---- causal mask (diagonal tiles only) ----
        if (kb + 63 > q0 + wq * 16) {
            #pragma unroll
            for (int t = 0; t < 8; t++) {
                int key = kb + t * 8 + 2 * tig;
                if (key     > row0)     s[t][0] = -INFINITY;
                if (key + 1 > row0)     s[t][1] = -INFINITY;
                if (key     > row0 + 8) s[t][2] = -INFINITY;
                if (key + 1 > row0 + 8) s[t][3] = -INFINITY;
            }
        }

        // ---- online softmax ----
        float r0 = -INFINITY, r1 = -INFINITY;
        #pragma unroll
        for (int t = 0; t < 8; t++) {
            r0 = fmaxf(r0, fmaxf(s[t][0], s[t][1]));
            r1 = fmaxf(r1, fmaxf(s[t][2], s[t][3]));
        }
        r0 = fmaxf(r0, __shfl_xor_sync(0xffffffffu, r0, 1));
        r0 = fmaxf(r0, __shfl_xor_sync(0xffffffffu, r0, 2));
        r1 = fmaxf(r1, __shfl_xor_sync(0xffffffffu, r1, 1));
        r1 = fmaxf(r1, __shfl_xor_sync(0xffffffffu, r1, 2));
        float mn0 = fmaxf(m0, r0), mn1 = fmaxf(m1, r1);
        float c0 = __expf(m0 - mn0), c1 = __expf(m1 - mn1);
        m0 = mn0; m1 = mn1;
        l0 *= c0;  l1 *= c1;
        #pragma unroll
        for (int t = 0; t < 8; t++) {
            s[t][0] = __expf(s[t][0] - m0);
            s[t][1] = __expf(s[t][1] - m0);
            s[t][2] = __expf(s[t][2] - m1);
            s[t][3] = __expf(s[t][3] - m1);
            l0 += s[t][0] + s[t][1];
            l1 += s[t][2] + s[t][3];
        }
        #pragma unroll
        for (int t = 0; t < 8; t++) {
            o[t][0] *= c0; o[t][1] *= c0;
            o[t][2] *= c1; o[t][3] *= c1;
        }

        // ---- pack P fp16 (C-frag == A-frag identity) ----
        uint32 p16[4][4];
        #pragma unroll
        for (int kk = 0; kk < 4; kk++) {
            p16[kk][0] = pack_h2(s[2*kk][0],   s[2*kk][1]);
            p16[kk][1] = pack_h2(s[2*kk][2],   s[2*kk][3]);
            p16[kk][2] = pack_h2(s[2*kk+1][0], s[2*kk+1][1]);
            p16[kk][3] = pack_h2(s[2*kk+1][2], s[2*kk+1][3]);
        }

        // ---- O += P V (single-term fp16) ----
        #pragma unroll
        for (int kk = 0; kk < 4; kk++) {
            uint32 v4[4][4];
            #pragma unroll
            for (int g = 0; g < 4; g++)
                ldsm_x4_t(v4[g], vbse + (uint32)(kk * 2304 + g * 32) + vOffBase);
            #pragma unroll
            for (int g = 0; g < 4; g++) {
                mma_f16(o[2*g],   p16[kk], v4[g][0], v4[g][1]);
                mma_f16(o[2*g+1], p16[kk], v4[g][2], v4[g][3]);
            }
        }
        __syncthreads();
    }

    // ---- finalize: reduce l across quad, normalize, fp16 store ----
    l0 += __shfl_xor_sync(0xffffffffu, l0, 1);
    l0 += __shfl_xor_sync(0xffffffffu, l0, 2);
    l1 += __shfl_xor_sync(0xffffffffu, l1, 1);
    l1 += __shfl_xor_sync(0xffffffffu, l1, 2);
    float i0 = 1.f / l0, i1 = 1.f / l1;
    #pragma unroll
    for (int t = 0; t < 8; t++) {
        int col = h * HD + t * 8 + 2 * tig;
        size_t d0 = ((size_t)(b * SEQ + row0)) * DMODEL + col;
        size_t d1 = ((size_t)(b * SEQ + row0 + 8)) * DMODEL + col;
        *(__half2*)&O16[d0] = __floats2half2_rn(o[t][0] * i0, o[t][1] * i0);
        *(__half2*)&O16[d1] = __floats2half2_rn(o[t][2] * i1, o[t][3] * i1);
    }
}

// ---------------------------------------------------------------------------
// Launch
// ---------------------------------------------------------------------------
extern "C" void kernel_launch(void* const* d_in, const int* in_sizes, int n_in,
                              void* d_out, int out_size)
{
    const float* hidden = (const float*)d_in[0];   // [B,S,D]
    const float* W_attn = (const float*)d_in[1];   // [D,3D]
    const float* b_attn = (const float*)d_in[2];   // [3D]
    const float* W_proj = (const float*)d_in[3];   // [D,D]
    const float* b_proj = (const float*)d_in[4];   // [D]
    float* out = (float*)d_out;                    // [B,S,D]

    __half *h16, *wa16, *wp16, *at16, *q16, *k16, *v16;
    cudaGetSymbolAddress((void**)&h16,  g_h16);
    cudaGetSymbolAddress((void**)&wa16, g_wa16);
    cudaGetSymbolAddress((void**)&wp16, g_wp16);
    cudaGetSymbolAddress((void**)&at16, g_at16);
    cudaGetSymbolAddress((void**)&q16,  g_q16);
    cudaGetSymbolAddress((void**)&k16,  g_k16);
    cudaGetSymbolAddress((void**)&v16,  g_v16);

    cudaFuncSetAttribute(gemm_fp16_kernel<0>,
                         cudaFuncAttributeMaxDynamicSharedMemorySize,
                         GEMM_SMEM_BYTES);
    cudaFuncSetAttribute(gemm_fp16_kernel<1>,
                         cudaFuncAttributeMaxDynamicSharedMemorySize,
                         GEMM_SMEM_BYTES);
    cudaFuncSetAttribute(attn_mma_kernel,
                         cudaFuncAttributeMaxDynamicSharedMemorySize,
                         ATTN_SMEM_BYTES);

    const int M = BATCH * SEQ;   // 4096

    // 0) fp32 -> fp16 converts (single fused launch)
    {
        int n0 = M * DMODEL;              // 4,194,304
        int n1 = DMODEL * 3 * DMODEL;     // 3,145,728
        int n2 = DMODEL * DMODEL;         // 1,048,576
        int total = n0 + n1 + n2;         // 8,388,608
        conv3_kernel<<<total / 1024, 256>>>(hidden, h16, n0,
                                            W_attn, wa16, n1,
                                            W_proj, wp16, n2);
    }
    // 1) QKV projection (fp16 mma) -> fp16 head-major q(scaled)/k/v
    {
        dim3 grid(3 * DMODEL / 128, M / 128);    // (24, 32)
        gemm_fp16_kernel<1><<<grid, 256, GEMM_SMEM_BYTES>>>(
            h16, wa16, b_attn, nullptr, q16, k16, v16, M, 3 * DMODEL, DMODEL);
    }
    // 2) causal attention (fully fp16 mma) -> fp16 output
    {
        dim3 grid(SEQ / 128, NHEAD, BATCH);      // (16, 16, 2)
        attn_mma_kernel<<<grid, 256, ATTN_SMEM_BYTES>>>(q16, k16, v16, at16);
    }
    // 3) output projection (fp16 mma) -> fp32 out
    {
        dim3 grid(DMODEL / 128, M / 128);        // (8, 32)
        gemm_fp16_kernel<0><<<grid, 256, GEMM_SMEM_BYTES>>>(
            at16, wp16, b_proj, out, nullptr, nullptr, nullptr,
            M, DMODEL, DMODEL);
    }
}